// round 1
// baseline (speedup 1.0000x reference)
#include <cuda_runtime.h>
#include <math.h>

// Shapes (fixed by the problem)
//   B=8, M=256, E=128, K=16, H=1024, A=256, R=1024, RMS=512
// Pipeline (algebraically restructured, exact):
//   g[b,m]   = Wa . ( tanh(Wv m + bv) * sigmoid(Wu m + bu) ) + ba        (per-mention scalar)
//   w[b,e,:] = softmax over K of masked g at entity indices
//   E[b,e,:] = sum_k w_k * mention[b, idx_k, :]
//   Cg       = RM^T RM            [512,512]
//   M2       = Wr Cg + br (x) colsum(RM)        [1024,512]
//   W_eff    = Wo1^T + M2 Wo2^T   [1024,1024]   (Wo1 = Wo[:, :H], Wo2 = Wo[:, H:])
//   out      = E W_eff + bo       [1024,1024]

// ---------------- scratch (device globals; no allocation) ----------------
__device__ float g_P[2048 * 512];      // pre-activation [Pv | Pu]
__device__ float g_score[2048];        // per-mention logits
__device__ float g_E[1024 * 1024];     // entity reprs
__device__ float g_part[8 * 512];      // colsum partials
__device__ float g_Cg[512 * 512];      // RM^T RM
__device__ float g_M2[1024 * 512];
__device__ float g_Weff[1024 * 1024];

// ---------------- generic tiled SGEMM: C[M,N] = op(A) * op(B) + epi ----------------
// BM=BN=64, BK=16, 256 threads, 4x4 microtile per thread.
// AT: A stored [K,M] (access A[k*lda+m]);  else A stored [M,K].
// BT: B stored [N,K] (access B[n*ldb+k]);  else B stored [K,N].
// EPI: 0 none; 1: +e1[n]; 2: +e1[n*eld+m]; 3: +e1[m]*sum_p e2[p*512+n]
template <int AT, int BT, int EPI>
__global__ __launch_bounds__(256) void sgemm64(
    const float* __restrict__ A, const float* __restrict__ B, float* __restrict__ C,
    int Kdim, int lda, int ldb, int ldc,
    const float* __restrict__ e1, const float* __restrict__ e2, int eld)
{
    __shared__ float As[16][68];
    __shared__ float Bs[16][68];
    const int t  = threadIdx.x;
    const int tx = t & 15, ty = t >> 4;
    const int m0 = blockIdx.y * 64;
    const int n0 = blockIdx.x * 64;

    float acc[4][4] = {};

    for (int k0 = 0; k0 < Kdim; k0 += 16) {
        if (!AT) {
            const int kk = t & 15, r0 = t >> 4;
#pragma unroll
            for (int q = 0; q < 4; q++) {
                const int r = r0 + q * 16;
                As[kk][r] = A[(size_t)(m0 + r) * lda + k0 + kk];
            }
        } else {
            const int mi = t & 63, kk0 = t >> 6;
#pragma unroll
            for (int q = 0; q < 4; q++) {
                const int kk = kk0 + q * 4;
                As[kk][mi] = A[(size_t)(k0 + kk) * lda + m0 + mi];
            }
        }
        if (!BT) {
            const int ni = t & 63, kk0 = t >> 6;
#pragma unroll
            for (int q = 0; q < 4; q++) {
                const int kk = kk0 + q * 4;
                Bs[kk][ni] = B[(size_t)(k0 + kk) * ldb + n0 + ni];
            }
        } else {
            const int kk = t & 15, nn0 = t >> 4;
#pragma unroll
            for (int q = 0; q < 4; q++) {
                const int ni = nn0 + q * 16;
                Bs[kk][ni] = B[(size_t)(n0 + ni) * ldb + k0 + kk];
            }
        }
        __syncthreads();
#pragma unroll
        for (int kk = 0; kk < 16; kk++) {
            float a4[4], b4[4];
#pragma unroll
            for (int i = 0; i < 4; i++) a4[i] = As[kk][ty * 4 + i];
#pragma unroll
            for (int j = 0; j < 4; j++) b4[j] = Bs[kk][tx * 4 + j];
#pragma unroll
            for (int i = 0; i < 4; i++)
#pragma unroll
                for (int j = 0; j < 4; j++)
                    acc[i][j] = fmaf(a4[i], b4[j], acc[i][j]);
        }
        __syncthreads();
    }

#pragma unroll
    for (int i = 0; i < 4; i++) {
        const int m = m0 + ty * 4 + i;
#pragma unroll
        for (int j = 0; j < 4; j++) {
            const int n = n0 + tx * 4 + j;
            float v = acc[i][j];
            if (EPI == 1) {
                v += e1[n];
            } else if (EPI == 2) {
                v += e1[(size_t)n * eld + m];
            } else if (EPI == 3) {
                float cs = 0.f;
#pragma unroll
                for (int p = 0; p < 8; p++) cs += e2[p * 512 + n];
                v = fmaf(e1[m], cs, v);
            }
            C[(size_t)m * ldc + n] = v;
        }
    }
}

// ---------------- score epilogue: g[row] = sum_a tanh(Pv+bv)*sig(Pu+bu)*Wa + ba ----------------
__global__ __launch_bounds__(256) void score_epilogue(
    const float* __restrict__ P, const float* __restrict__ bv,
    const float* __restrict__ bu, const float* __restrict__ Wa,
    const float* __restrict__ ba, float* __restrict__ g)
{
    const int warp = threadIdx.x >> 5, lane = threadIdx.x & 31;
    const int row = blockIdx.x * 8 + warp;
    const float* pr = P + (size_t)row * 512;
    float s = 0.f;
#pragma unroll
    for (int q = 0; q < 8; q++) {
        const int c = lane + q * 32;
        const float v = tanhf(pr[c] + bv[c]);
        float u = pr[256 + c] + bu[c];
        u = 1.f / (1.f + expf(-u));
        s += v * u * Wa[c];
    }
#pragma unroll
    for (int o = 16; o; o >>= 1) s += __shfl_xor_sync(0xffffffffu, s, o);
    if (lane == 0) g[row] = s + ba[0];
}

// ---------------- masked softmax over K=16 + weighted pooling ----------------
__global__ __launch_bounds__(128) void pool_kernel(
    const float* __restrict__ mention, const int* __restrict__ entities,
    const int* __restrict__ masks, const float* __restrict__ g,
    float* __restrict__ Ebuf)
{
    const int be = blockIdx.x;     // b*128 + e
    const int b = be >> 7;
    __shared__ float w[16];
    __shared__ int idx[16];
    const int tid = threadIdx.x;
    if (tid < 16) {
        const int id = entities[(size_t)be * 16 + tid];
        idx[tid] = id;
        const int mk = masks[(size_t)be * 16 + tid];
        w[tid] = mk ? g[b * 256 + id] : -1e25f;
    }
    __syncthreads();
    if (tid == 0) {
        float mx = -INFINITY;
#pragma unroll
        for (int k = 0; k < 16; k++) mx = fmaxf(mx, w[k]);
        float e[16];
        float sum = 0.f;
#pragma unroll
        for (int k = 0; k < 16; k++) { e[k] = expf(w[k] - mx); sum += e[k]; }
        const float inv = 1.f / sum;
#pragma unroll
        for (int k = 0; k < 16; k++) w[k] = e[k] * inv;
    }
    __syncthreads();
    const float* mb = mention + (size_t)b * 256 * 1024;
#pragma unroll
    for (int q = 0; q < 8; q++) {
        const int h = tid + q * 128;
        float acc = 0.f;
#pragma unroll
        for (int k = 0; k < 16; k++)
            acc = fmaf(w[k], mb[(size_t)idx[k] * 1024 + h], acc);
        Ebuf[(size_t)be * 1024 + h] = acc;
    }
}

// ---------------- colsum partials of RM: part[p][j] = sum over 128 rows ----------------
__global__ __launch_bounds__(512) void colsum_part(
    const float* __restrict__ RM, float* __restrict__ part)
{
    const int j = threadIdx.x;     // 512 columns
    const int p = blockIdx.x;      // 8 row-chunks of 128
    float s = 0.f;
#pragma unroll 4
    for (int r = 0; r < 128; r++) s += RM[(size_t)(p * 128 + r) * 512 + j];
    part[p * 512 + j] = s;
}

extern "C" void kernel_launch(void* const* d_in, const int* in_sizes, int n_in,
                              void* d_out, int out_size)
{
    const float* mention  = (const float*)d_in[0];   // [8,256,1024]
    const int*   entities = (const int*)d_in[1];     // [8,128,16]
    const int*   masks    = (const int*)d_in[2];     // [8,128,16]
    const float* RM       = (const float*)d_in[3];   // [1024,512]
    const float* Wv       = (const float*)d_in[4];   // [256,1024]
    const float* bv       = (const float*)d_in[5];
    const float* Wu       = (const float*)d_in[6];   // [256,1024]
    const float* bu       = (const float*)d_in[7];
    const float* Wa       = (const float*)d_in[8];   // [1,256]
    const float* ba       = (const float*)d_in[9];
    const float* Wr       = (const float*)d_in[10];  // [1024,512]
    const float* br       = (const float*)d_in[11];
    const float* Wo       = (const float*)d_in[12];  // [1024,1536]
    const float* bo       = (const float*)d_in[13];
    float* out = (float*)d_out;

    float *P, *score, *Ebuf, *part, *Cg, *M2, *Weff;
    cudaGetSymbolAddress((void**)&P,     g_P);
    cudaGetSymbolAddress((void**)&score, g_score);
    cudaGetSymbolAddress((void**)&Ebuf,  g_E);
    cudaGetSymbolAddress((void**)&part,  g_part);
    cudaGetSymbolAddress((void**)&Cg,    g_Cg);
    cudaGetSymbolAddress((void**)&M2,    g_M2);
    cudaGetSymbolAddress((void**)&Weff,  g_Weff);

    // 1) P = [mention @ Wv^T | mention @ Wu^T]   (2048 x 512, pre-activation)
    sgemm64<0, 1, 0><<<dim3(4, 32), 256>>>(mention, Wv, P,       1024, 1024, 1024, 512, nullptr, nullptr, 0);
    sgemm64<0, 1, 0><<<dim3(4, 32), 256>>>(mention, Wu, P + 256, 1024, 1024, 1024, 512, nullptr, nullptr, 0);

    // 2) per-mention gate score g[2048]
    score_epilogue<<<256, 256>>>(P, bv, bu, Wa, ba, score);

    // 3) masked softmax over K + weighted pooling -> E[1024,1024]
    pool_kernel<<<1024, 128>>>(mention, entities, masks, score, Ebuf);

    // 4) colsum(RM) partials (8 x 512)
    colsum_part<<<8, 512>>>(RM, part);

    // 5) Cg = RM^T @ RM  [512,512]
    sgemm64<1, 0, 0><<<dim3(8, 8), 256>>>(RM, RM, Cg, 1024, 512, 512, 512, nullptr, nullptr, 0);

    // 6) M2 = Wr @ Cg + br (x) colsum  [1024,512]
    sgemm64<0, 0, 3><<<dim3(8, 16), 256>>>(Wr, Cg, M2, 512, 512, 512, 512, br, part, 0);

    // 7) W_eff = M2 @ Wo2^T + Wo1^T  [1024,1024]
    sgemm64<0, 1, 2><<<dim3(16, 16), 256>>>(M2, Wo + 1024, Weff, 512, 512, 1536, 1024, Wo, nullptr, 1536);

    // 8) out = E @ W_eff + bo  [1024,1024]
    sgemm64<0, 0, 1><<<dim3(16, 16), 256>>>(Ebuf, Weff, out, 1024, 1024, 1024, 1024, bo, nullptr, 0);
}

// round 3
// speedup vs baseline: 1.6990x; 1.6990x over previous
#include <cuda_runtime.h>
#include <cuda_bf16.h>
#include <stdint.h>
#include <math.h>

// ============================================================================
// Shapes: B=8, M=256, E=128, K=16, H=1024, A=256, R=1024, RMS=512
// Restructured (exact):
//   P[2048,512]  = mention[2048,1024] @ [Wv;Wu][512,1024]^T
//   g[2048]      = Wa . (tanh(Pv+bv) * sigmoid(Pu+bu)) + ba
//   E[1024,1024] = softmax-pooled mention rows (per (b,e), K=16)
//   Cg[512,512]  = RMT @ RMT^T  (RMT = RM^T)
//   M2[1024,512] = Wr Cg + br (x) colsum(RM)
//   WT[1024,1024]= Wo2 M2^T + Wo1   (WT = Weff^T)
//   out[1024,1024] = E WT^T + bo
// GEMMs: C = A[M,K]*B[N,K]^T via mma.sync.m16n8k16.bf16, bf16x3 hi/lo split.
// ============================================================================

__device__ __nv_bfloat16 g_mhi[2048*1024], g_mlo[2048*1024];
__device__ __nv_bfloat16 g_wvuh[512*1024], g_wvul[512*1024];
__device__ __nv_bfloat16 g_rmth[512*1024], g_rmtl[512*1024];
__device__ __nv_bfloat16 g_wrh[1024*512],  g_wrl[1024*512];
__device__ __nv_bfloat16 g_wo2h[1024*512], g_wo2l[1024*512];
__device__ __nv_bfloat16 g_cgh[512*512],   g_cgl[512*512];
__device__ __nv_bfloat16 g_m2h[1024*512],  g_m2l[1024*512];
__device__ __nv_bfloat16 g_wth[1024*1024], g_wtl[1024*1024];
__device__ __nv_bfloat16 g_eh[1024*1024],  g_el[1024*1024];
__device__ float g_P[2048*512];
__device__ float g_score[2048];
__device__ float g_part[8*512];

__device__ __forceinline__ uint32_t smem_u32(const void* p) {
    uint32_t a;
    asm("{ .reg .u64 t; cvta.to.shared.u64 t, %1; cvt.u32.u64 %0, t; }" : "=r"(a) : "l"(p));
    return a;
}

#define CP16(dst, src) \
    asm volatile("cp.async.cg.shared.global [%0], [%1], 16;" :: "r"(dst), "l"(src))
#define CP_COMMIT() asm volatile("cp.async.commit_group;" ::: "memory")
#define CP_WAIT(n)  asm volatile("cp.async.wait_group %0;" :: "n"(n) : "memory")

#define LDSM4(r0, r1, r2, r3, addr) \
    asm volatile("ldmatrix.sync.aligned.m8n8.x4.shared.b16 {%0,%1,%2,%3}, [%4];" \
        : "=r"(r0), "=r"(r1), "=r"(r2), "=r"(r3) : "r"(addr))

__device__ __forceinline__ void mma16816(float* c, const uint32_t* a, const uint32_t* b) {
    asm volatile("mma.sync.aligned.m16n8k16.row.col.f32.bf16.bf16.f32 "
        "{%0,%1,%2,%3}, {%4,%5,%6,%7}, {%8,%9}, {%0,%1,%2,%3};"
        : "+f"(c[0]), "+f"(c[1]), "+f"(c[2]), "+f"(c[3])
        : "r"(a[0]), "r"(a[1]), "r"(a[2]), "r"(a[3]), "r"(b[0]), "r"(b[1]));
}

// ---------------- GEMM: 128x128 block, BK=32, 8 warps, 3-stage cp.async ----
// smem tile: 128 rows x 40 bf16 (80B padded rows, ldmatrix conflict-free)
#define TSTRIDE 80
#define TILEB   (128 * TSTRIDE)       // 10240
#define STAGEB  (4 * TILEB)           // 40960: Ah, Al, Bh, Bl
#define NSTAGE  3
#define SMEM_GEMM (NSTAGE * STAGEB)   // 122880

enum { EP_F32 = 0, EP_HILO = 1, EP_M2 = 2, EP_WEFFT = 3, EP_OUT = 4 };

__device__ __forceinline__ void issue_tile(uint32_t sdst,
        const __nv_bfloat16* __restrict__ G, int ld, int r0, int k0, int t) {
#pragma unroll
    for (int q = 0; q < 2; q++) {
        const int idx = t + (q << 8);
        const int r = idx >> 2, ch = idx & 3;
        CP16(sdst + r * TSTRIDE + ch * 16,
             G + (size_t)(r0 + r) * ld + k0 + ch * 8);
    }
}

__device__ __forceinline__ void store_hilo(__nv_bfloat16* Ch, __nv_bfloat16* Cl,
        int ldc, int row, int col, float v0, float v1) {
    __nv_bfloat16 h0 = __float2bfloat16(v0);
    __nv_bfloat16 h1 = __float2bfloat16(v1);
    __nv_bfloat162 hp; hp.x = h0; hp.y = h1;
    __nv_bfloat162 lp;
    lp.x = __float2bfloat16(v0 - __bfloat162float(h0));
    lp.y = __float2bfloat16(v1 - __bfloat162float(h1));
    *(__nv_bfloat162*)(Ch + (size_t)row * ldc + col) = hp;
    *(__nv_bfloat162*)(Cl + (size_t)row * ldc + col) = lp;
}

template <int EPI>
__global__ __launch_bounds__(256, 1)
void gemm_bf16x3(
    const __nv_bfloat16* __restrict__ Ah, const __nv_bfloat16* __restrict__ Al, int lda,
    const __nv_bfloat16* __restrict__ Bh, const __nv_bfloat16* __restrict__ Bl, int ldb,
    int Kdim,
    float* __restrict__ Cf, __nv_bfloat16* __restrict__ Ch, __nv_bfloat16* __restrict__ Cl,
    int ldc,
    const float* __restrict__ aux1, const float* __restrict__ aux2, int auxld)
{
    extern __shared__ __align__(128) char sm[];
    const uint32_t sbase = smem_u32(sm);
    const int t = threadIdx.x, lane = t & 31, wid = t >> 5;
    const int wm = wid >> 2, wn = wid & 3;   // 2 x 4 warp grid
    const int m0 = blockIdx.y * 128, n0 = blockIdx.x * 128;
    const int nch = Kdim >> 5;

    float acc[4][4][4] = {};   // [mi][nj][4]

    // prologue: chunks 0 and 1
#pragma unroll
    for (int c = 0; c < 2; c++) {
        const uint32_t sb = sbase + c * STAGEB;
        issue_tile(sb + 0 * TILEB, Ah, lda, m0, c * 32, t);
        issue_tile(sb + 1 * TILEB, Al, lda, m0, c * 32, t);
        issue_tile(sb + 2 * TILEB, Bh, ldb, n0, c * 32, t);
        issue_tile(sb + 3 * TILEB, Bl, ldb, n0, c * 32, t);
        CP_COMMIT();
    }

    // ldmatrix per-lane address offsets (within a tile)
    const uint32_t a_off = (uint32_t)((lane & 15) * TSTRIDE + (lane >> 4) * 16);
    const uint32_t b_off = (uint32_t)(((lane & 7) + ((lane >> 4) & 1) * 8) * TSTRIDE
                                      + ((lane >> 3) & 1) * 16);

    for (int c = 0; c < nch; c++) {
        CP_WAIT(1);
        __syncthreads();
        // prefetch chunk c+2
        if (c + 2 < nch) {
            const uint32_t sb = sbase + ((c + 2) % NSTAGE) * STAGEB;
            issue_tile(sb + 0 * TILEB, Ah, lda, m0, (c + 2) * 32, t);
            issue_tile(sb + 1 * TILEB, Al, lda, m0, (c + 2) * 32, t);
            issue_tile(sb + 2 * TILEB, Bh, ldb, n0, (c + 2) * 32, t);
            issue_tile(sb + 3 * TILEB, Bl, ldb, n0, (c + 2) * 32, t);
        }
        CP_COMMIT();

        const uint32_t sb = sbase + (c % NSTAGE) * STAGEB;
        const uint32_t sAh = sb + 0 * TILEB + wm * 64 * TSTRIDE;
        const uint32_t sAl = sb + 1 * TILEB + wm * 64 * TSTRIDE;
        const uint32_t sBh = sb + 2 * TILEB + wn * 32 * TSTRIDE;
        const uint32_t sBl = sb + 3 * TILEB + wn * 32 * TSTRIDE;

#pragma unroll
        for (int ks = 0; ks < 2; ks++) {
            uint32_t fAh[4][4], fAl[4][4], fBh[4][2], fBl[4][2];
#pragma unroll
            for (int mi = 0; mi < 4; mi++) {
                const uint32_t ao = a_off + mi * 16 * TSTRIDE + ks * 32;
                LDSM4(fAh[mi][0], fAh[mi][1], fAh[mi][2], fAh[mi][3], sAh + ao);
                LDSM4(fAl[mi][0], fAl[mi][1], fAl[mi][2], fAl[mi][3], sAl + ao);
            }
#pragma unroll
            for (int np = 0; np < 2; np++) {
                const uint32_t bo = b_off + np * 16 * TSTRIDE + ks * 32;
                LDSM4(fBh[np*2][0], fBh[np*2][1], fBh[np*2+1][0], fBh[np*2+1][1], sBh + bo);
                LDSM4(fBl[np*2][0], fBl[np*2][1], fBl[np*2+1][0], fBl[np*2+1][1], sBl + bo);
            }
#pragma unroll
            for (int mi = 0; mi < 4; mi++)
#pragma unroll
                for (int nj = 0; nj < 4; nj++) {
                    mma16816(acc[mi][nj], fAh[mi], fBh[nj]);
                    mma16816(acc[mi][nj], fAh[mi], fBl[nj]);
                    mma16816(acc[mi][nj], fAl[mi], fBh[nj]);
                }
        }
    }

    __syncthreads();   // done with smem tiles

    float* smf = (float*)sm;   // reuse for EP_M2 colsum
    if (EPI == EP_M2) {
        if (t < 128) {
            float s = 0.f;
#pragma unroll
            for (int p = 0; p < 8; p++) s += aux2[p * 512 + n0 + t];
            smf[t] = s;
        }
        __syncthreads();
    }

    const int g = lane >> 2, tq = lane & 3;
#pragma unroll
    for (int mi = 0; mi < 4; mi++) {
#pragma unroll
        for (int nj = 0; nj < 4; nj++) {
            const int row = m0 + wm * 64 + mi * 16 + g;
            const int col = n0 + wn * 32 + nj * 8 + tq * 2;
            float v00 = acc[mi][nj][0], v01 = acc[mi][nj][1];
            float v10 = acc[mi][nj][2], v11 = acc[mi][nj][3];
            if (EPI == EP_F32) {
                *(float2*)(Cf + (size_t)row * ldc + col) = make_float2(v00, v01);
                *(float2*)(Cf + (size_t)(row + 8) * ldc + col) = make_float2(v10, v11);
            } else if (EPI == EP_OUT) {
                const float b0 = aux1[col], b1 = aux1[col + 1];
                *(float2*)(Cf + (size_t)row * ldc + col) = make_float2(v00 + b0, v01 + b1);
                *(float2*)(Cf + (size_t)(row + 8) * ldc + col) = make_float2(v10 + b0, v11 + b1);
            } else {
                if (EPI == EP_M2) {
                    const float c0 = smf[col - n0], c1 = smf[col - n0 + 1];
                    const float bm0 = aux1[row], bm8 = aux1[row + 8];
                    v00 = fmaf(bm0, c0, v00); v01 = fmaf(bm0, c1, v01);
                    v10 = fmaf(bm8, c0, v10); v11 = fmaf(bm8, c1, v11);
                } else if (EPI == EP_WEFFT) {
                    v00 += aux1[(size_t)row * auxld + col];
                    v01 += aux1[(size_t)row * auxld + col + 1];
                    v10 += aux1[(size_t)(row + 8) * auxld + col];
                    v11 += aux1[(size_t)(row + 8) * auxld + col + 1];
                }
                store_hilo(Ch, Cl, ldc, row, col, v00, v01);
                store_hilo(Ch, Cl, ldc, row + 8, col, v10, v11);
            }
        }
    }
}

// ---------------- fp32 -> (hi, lo) bf16 conversion ----------------
__global__ __launch_bounds__(256) void conv_hilo(
    const float* __restrict__ src, int ld, int cols4,
    __nv_bfloat16* __restrict__ dh, __nv_bfloat16* __restrict__ dl)
{
    const int i = blockIdx.x * 256 + threadIdx.x;
    const int r = i / cols4, c = i % cols4;
    float4 v = *(const float4*)(src + (size_t)r * ld + c * 4);
    const size_t o = ((size_t)r * cols4 + c) * 4;
    const float* vv = (const float*)&v;
#pragma unroll
    for (int x = 0; x < 4; x += 2) {
        __nv_bfloat16 h0 = __float2bfloat16(vv[x]);
        __nv_bfloat16 h1 = __float2bfloat16(vv[x + 1]);
        __nv_bfloat162 hp; hp.x = h0; hp.y = h1;
        __nv_bfloat162 lp;
        lp.x = __float2bfloat16(vv[x] - __bfloat162float(h0));
        lp.y = __float2bfloat16(vv[x + 1] - __bfloat162float(h1));
        *(__nv_bfloat162*)(dh + o + x) = hp;
        *(__nv_bfloat162*)(dl + o + x) = lp;
    }
}

// RM[1024,512] -> RMT[512,1024] hi/lo (tiled transpose)
__global__ __launch_bounds__(256) void convT_hilo(
    const float* __restrict__ RM, __nv_bfloat16* __restrict__ dh, __nv_bfloat16* __restrict__ dl)
{
    __shared__ float tb[32][33];
    const int tx = threadIdx.x, ty = threadIdx.y;
    const int k0 = blockIdx.x * 32, i0 = blockIdx.y * 32;
#pragma unroll
    for (int q = 0; q < 4; q++)
        tb[ty + q * 8][tx] = RM[(size_t)(k0 + ty + q * 8) * 512 + i0 + tx];
    __syncthreads();
#pragma unroll
    for (int q = 0; q < 4; q++) {
        float v = tb[tx][ty + q * 8];
        size_t o = (size_t)(i0 + ty + q * 8) * 1024 + k0 + tx;
        __nv_bfloat16 h = __float2bfloat16(v);
        dh[o] = h;
        dl[o] = __float2bfloat16(v - __bfloat162float(h));
    }
}

// ---------------- score epilogue ----------------
__global__ __launch_bounds__(256) void score_epilogue(
    const float* __restrict__ P, const float* __restrict__ bv,
    const float* __restrict__ bu, const float* __restrict__ Wa,
    const float* __restrict__ ba, float* __restrict__ g)
{
    const int warp = threadIdx.x >> 5, lane = threadIdx.x & 31;
    const int row = blockIdx.x * 8 + warp;
    const float* pr = P + (size_t)row * 512;
    float s = 0.f;
#pragma unroll
    for (int q = 0; q < 8; q++) {
        const int c = lane + q * 32;
        const float v = tanhf(pr[c] + bv[c]);
        float u = pr[256 + c] + bu[c];
        u = 1.f / (1.f + expf(-u));
        s += v * u * Wa[c];
    }
#pragma unroll
    for (int o = 16; o; o >>= 1) s += __shfl_xor_sync(0xffffffffu, s, o);
    if (lane == 0) g[row] = s + ba[0];
}

// ---------------- softmax-pool -> E hi/lo ----------------
__global__ __launch_bounds__(256) void pool2(
    const float* __restrict__ mention, const int* __restrict__ ent,
    const int* __restrict__ msk, const float* __restrict__ g,
    __nv_bfloat16* __restrict__ Eh, __nv_bfloat16* __restrict__ El)
{
    const int be = blockIdx.x, b = be >> 7, tid = threadIdx.x;
    __shared__ float w[16];
    __shared__ int idx[16];
    if (tid < 16) {
        const int id = ent[(size_t)be * 16 + tid];
        idx[tid] = id;
        w[tid] = msk[(size_t)be * 16 + tid] ? g[b * 256 + id] : -1e25f;
    }
    __syncthreads();
    if (tid == 0) {
        float mx = -INFINITY;
#pragma unroll
        for (int k = 0; k < 16; k++) mx = fmaxf(mx, w[k]);
        float e[16], sum = 0.f;
#pragma unroll
        for (int k = 0; k < 16; k++) { e[k] = expf(w[k] - mx); sum += e[k]; }
        const float inv = 1.f / sum;
#pragma unroll
        for (int k = 0; k < 16; k++) w[k] = e[k] * inv;
    }
    __syncthreads();
    const float* mb = mention + (size_t)b * 256 * 1024;
    const int h0 = tid * 4;
    float4 acc = make_float4(0.f, 0.f, 0.f, 0.f);
#pragma unroll
    for (int k = 0; k < 16; k++) {
        const float4 v = *(const float4*)(mb + (size_t)idx[k] * 1024 + h0);
        const float wk = w[k];
        acc.x = fmaf(wk, v.x, acc.x);
        acc.y = fmaf(wk, v.y, acc.y);
        acc.z = fmaf(wk, v.z, acc.z);
        acc.w = fmaf(wk, v.w, acc.w);
    }
    const size_t o = (size_t)be * 1024 + h0;
    const float* av = (const float*)&acc;
#pragma unroll
    for (int x = 0; x < 4; x += 2) {
        __nv_bfloat16 h0b = __float2bfloat16(av[x]);
        __nv_bfloat16 h1b = __float2bfloat16(av[x + 1]);
        __nv_bfloat162 hp; hp.x = h0b; hp.y = h1b;
        __nv_bfloat162 lp;
        lp.x = __float2bfloat16(av[x] - __bfloat162float(h0b));
        lp.y = __float2bfloat16(av[x + 1] - __bfloat162float(h1b));
        *(__nv_bfloat162*)(Eh + o + x) = hp;
        *(__nv_bfloat162*)(El + o + x) = lp;
    }
}

// ---------------- colsum partials of RM ----------------
__global__ __launch_bounds__(512) void colsum_part(
    const float* __restrict__ RM, float* __restrict__ part)
{
    const int j = threadIdx.x;
    const int p = blockIdx.x;
    float s = 0.f;
#pragma unroll 4
    for (int r = 0; r < 128; r++) s += RM[(size_t)(p * 128 + r) * 512 + j];
    part[p * 512 + j] = s;
}

// ---------------- launch ----------------
extern "C" void kernel_launch(void* const* d_in, const int* in_sizes, int n_in,
                              void* d_out, int out_size)
{
    const float* mention  = (const float*)d_in[0];
    const int*   entities = (const int*)d_in[1];
    const int*   masks    = (const int*)d_in[2];
    const float* RM       = (const float*)d_in[3];
    const float* Wv       = (const float*)d_in[4];
    const float* bv       = (const float*)d_in[5];
    const float* Wu       = (const float*)d_in[6];
    const float* bu       = (const float*)d_in[7];
    const float* Wa       = (const float*)d_in[8];
    const float* ba       = (const float*)d_in[9];
    const float* Wr       = (const float*)d_in[10];
    const float* br       = (const float*)d_in[11];
    const float* Wo       = (const float*)d_in[12];
    const float* bo       = (const float*)d_in[13];
    float* out = (float*)d_out;

    __nv_bfloat16 *mhi, *mlo, *wvuh, *wvul, *rmth, *rmtl, *wrh, *wrl, *wo2h, *wo2l;
    __nv_bfloat16 *cgh, *cgl, *m2h, *m2l, *wth, *wtl, *eh, *el;
    float *P, *score, *part;
    cudaGetSymbolAddress((void**)&mhi, g_mhi);   cudaGetSymbolAddress((void**)&mlo, g_mlo);
    cudaGetSymbolAddress((void**)&wvuh, g_wvuh); cudaGetSymbolAddress((void**)&wvul, g_wvul);
    cudaGetSymbolAddress((void**)&rmth, g_rmth); cudaGetSymbolAddress((void**)&rmtl, g_rmtl);
    cudaGetSymbolAddress((void**)&wrh, g_wrh);   cudaGetSymbolAddress((void**)&wrl, g_wrl);
    cudaGetSymbolAddress((void**)&wo2h, g_wo2h); cudaGetSymbolAddress((void**)&wo2l, g_wo2l);
    cudaGetSymbolAddress((void**)&cgh, g_cgh);   cudaGetSymbolAddress((void**)&cgl, g_cgl);
    cudaGetSymbolAddress((void**)&m2h, g_m2h);   cudaGetSymbolAddress((void**)&m2l, g_m2l);
    cudaGetSymbolAddress((void**)&wth, g_wth);   cudaGetSymbolAddress((void**)&wtl, g_wtl);
    cudaGetSymbolAddress((void**)&eh, g_eh);     cudaGetSymbolAddress((void**)&el, g_el);
    cudaGetSymbolAddress((void**)&P, g_P);
    cudaGetSymbolAddress((void**)&score, g_score);
    cudaGetSymbolAddress((void**)&part, g_part);

    cudaFuncSetAttribute(gemm_bf16x3<EP_F32>,   cudaFuncAttributeMaxDynamicSharedMemorySize, SMEM_GEMM);
    cudaFuncSetAttribute(gemm_bf16x3<EP_HILO>,  cudaFuncAttributeMaxDynamicSharedMemorySize, SMEM_GEMM);
    cudaFuncSetAttribute(gemm_bf16x3<EP_M2>,    cudaFuncAttributeMaxDynamicSharedMemorySize, SMEM_GEMM);
    cudaFuncSetAttribute(gemm_bf16x3<EP_WEFFT>, cudaFuncAttributeMaxDynamicSharedMemorySize, SMEM_GEMM);
    cudaFuncSetAttribute(gemm_bf16x3<EP_OUT>,   cudaFuncAttributeMaxDynamicSharedMemorySize, SMEM_GEMM);

    // input conversions to hi/lo bf16
    conv_hilo<<<2048, 256>>>(mention, 1024, 256, mhi, mlo);
    conv_hilo<<<256,  256>>>(Wv, 1024, 256, wvuh, wvul);
    conv_hilo<<<256,  256>>>(Wu, 1024, 256, wvuh + 256*1024, wvul + 256*1024);
    conv_hilo<<<512,  256>>>(Wr, 512, 128, wrh, wrl);
    conv_hilo<<<512,  256>>>(Wo + 1024, 1536, 128, wo2h, wo2l);
    convT_hilo<<<dim3(32, 16), dim3(32, 8)>>>(RM, rmth, rmtl);
    colsum_part<<<8, 512>>>(RM, part);

    // P = mention @ Wvu^T  [2048,512]
    gemm_bf16x3<EP_F32><<<dim3(4, 16), 256, SMEM_GEMM>>>(
        mhi, mlo, 1024, wvuh, wvul, 1024, 1024, P, nullptr, nullptr, 512,
        nullptr, nullptr, 0);
    score_epilogue<<<256, 256>>>(P, bv, bu, Wa, ba, score);
    pool2<<<1024, 256>>>(mention, entities, masks, score, eh, el);

    // Cg = RMT @ RMT^T  [512,512]
    gemm_bf16x3<EP_HILO><<<dim3(4, 4), 256, SMEM_GEMM>>>(
        rmth, rmtl, 1024, rmth, rmtl, 1024, 1024, nullptr, cgh, cgl, 512,
        nullptr, nullptr, 0);
    // M2 = Wr @ Cg^T + br (x) colsum   (Cg symmetric)
    gemm_bf16x3<EP_M2><<<dim3(4, 8), 256, SMEM_GEMM>>>(
        wrh, wrl, 512, cgh, cgl, 512, 512, nullptr, m2h, m2l, 512,
        br, part, 0);
    // WT = Wo2 @ M2^T + Wo1  [1024,1024]
    gemm_bf16x3<EP_WEFFT><<<dim3(8, 8), 256, SMEM_GEMM>>>(
        wo2h, wo2l, 512, m2h, m2l, 512, 512, nullptr, wth, wtl, 1024,
        Wo, nullptr, 1536);
    // out = E @ WT^T + bo  [1024,1024]
    gemm_bf16x3<EP_OUT><<<dim3(8, 8), 256, SMEM_GEMM>>>(
        eh, el, 1024, wth, wtl, 1024, 1024, out, nullptr, nullptr, 1024,
        bo, nullptr, 0);
}

// round 4
// speedup vs baseline: 3.0624x; 1.8025x over previous
#include <cuda_runtime.h>
#include <cuda_bf16.h>
#include <stdint.h>
#include <math.h>

// ============================================================================
// Shapes: B=8, M=256, E=128, K=16, H=1024, A=256, R=1024, RMS=512
//   P[2048,512]  = mention @ [Wv;Wu]^T ;  g = Wa.(tanh(Pv+bv)*sig(Pu+bu))+ba
//   E[1024,1024] = softmax-pooled mention rows
//   Cg = RMT@RMT^T ; M2 = Wr Cg + br(x)colsum(RM) ; WT = Wo2 M2^T + Wo1
//   out = E WT^T + bo
// GEMMs: C = A[M,K]*B[N,K]^T via mma.m16n8k16.bf16, bf16x3 hi/lo split.
// Block tile 128x64, BK=32, 8 warps (4x2), warp tile 32x32, 3-stage cp.async.
// Two streams: attention chain on legacy, relation chain on side stream.
// ============================================================================

__device__ __nv_bfloat16 g_mhi[2048*1024], g_mlo[2048*1024];
__device__ __nv_bfloat16 g_wvuh[512*1024], g_wvul[512*1024];
__device__ __nv_bfloat16 g_rmth[512*1024], g_rmtl[512*1024];
__device__ __nv_bfloat16 g_wrh[1024*512],  g_wrl[1024*512];
__device__ __nv_bfloat16 g_wo2h[1024*512], g_wo2l[1024*512];
__device__ __nv_bfloat16 g_cgh[512*512],   g_cgl[512*512];
__device__ __nv_bfloat16 g_m2h[1024*512],  g_m2l[1024*512];
__device__ __nv_bfloat16 g_wth[1024*1024], g_wtl[1024*1024];
__device__ __nv_bfloat16 g_eh[1024*1024],  g_el[1024*1024];
__device__ float g_P[2048*512];
__device__ float g_score[2048];
__device__ float g_part[8*512];

// host-side streams/events (created at load; host objects only, no dev mem)
static cudaStream_t s_rel;
static cudaEvent_t  e_fork, e_rel;
static struct StreamInit {
    StreamInit() {
        cudaStreamCreateWithFlags(&s_rel, cudaStreamNonBlocking);
        cudaEventCreateWithFlags(&e_fork, cudaEventDisableTiming);
        cudaEventCreateWithFlags(&e_rel,  cudaEventDisableTiming);
    }
} s_init;

__device__ __forceinline__ uint32_t smem_u32(const void* p) {
    uint32_t a;
    asm("{ .reg .u64 t; cvta.to.shared.u64 t, %1; cvt.u32.u64 %0, t; }" : "=r"(a) : "l"(p));
    return a;
}

#define CP16(dst, src) \
    asm volatile("cp.async.cg.shared.global [%0], [%1], 16;" :: "r"(dst), "l"(src))
#define CP_COMMIT() asm volatile("cp.async.commit_group;" ::: "memory")
#define CP_WAIT(n)  asm volatile("cp.async.wait_group %0;" :: "n"(n) : "memory")

#define LDSM4(r0, r1, r2, r3, addr) \
    asm volatile("ldmatrix.sync.aligned.m8n8.x4.shared.b16 {%0,%1,%2,%3}, [%4];" \
        : "=r"(r0), "=r"(r1), "=r"(r2), "=r"(r3) : "r"(addr))

__device__ __forceinline__ void mma16816(float* c, const uint32_t* a, const uint32_t* b) {
    asm volatile("mma.sync.aligned.m16n8k16.row.col.f32.bf16.bf16.f32 "
        "{%0,%1,%2,%3}, {%4,%5,%6,%7}, {%8,%9}, {%0,%1,%2,%3};"
        : "+f"(c[0]), "+f"(c[1]), "+f"(c[2]), "+f"(c[3])
        : "r"(a[0]), "r"(a[1]), "r"(a[2]), "r"(a[3]), "r"(b[0]), "r"(b[1]));
}

// ---------------- GEMM: 128x64 block, BK=32, 8 warps (4x2), 3-stage --------
#define TSTRIDE 80
#define ATILEB  (128 * TSTRIDE)            // 10240
#define BTILEB  (64 * TSTRIDE)             // 5120
#define STAGEB  (2 * ATILEB + 2 * BTILEB)  // 30720: Ah, Al, Bh, Bl
#define NSTAGE  3
#define SMEM_GEMM (NSTAGE * STAGEB)        // 92160

#define OFF_AH 0
#define OFF_AL ATILEB
#define OFF_BH (2 * ATILEB)
#define OFF_BL (2 * ATILEB + BTILEB)

enum { EP_F32 = 0, EP_HILO = 1, EP_M2 = 2, EP_WEFFT = 3, EP_OUT = 4 };

__device__ __forceinline__ void issue_tileA(uint32_t sdst,
        const __nv_bfloat16* __restrict__ G, int ld, int r0, int k0, int t) {
#pragma unroll
    for (int q = 0; q < 2; q++) {
        const int idx = t + (q << 8);
        const int r = idx >> 2, ch = idx & 3;
        CP16(sdst + r * TSTRIDE + ch * 16,
             G + (size_t)(r0 + r) * ld + k0 + ch * 8);
    }
}
__device__ __forceinline__ void issue_tileB(uint32_t sdst,
        const __nv_bfloat16* __restrict__ G, int ld, int r0, int k0, int t) {
    const int r = t >> 2, ch = t & 3;
    CP16(sdst + r * TSTRIDE + ch * 16,
         G + (size_t)(r0 + r) * ld + k0 + ch * 8);
}

__device__ __forceinline__ void store_hilo(__nv_bfloat16* Ch, __nv_bfloat16* Cl,
        int ldc, int row, int col, float v0, float v1) {
    __nv_bfloat16 h0 = __float2bfloat16(v0);
    __nv_bfloat16 h1 = __float2bfloat16(v1);
    __nv_bfloat162 hp; hp.x = h0; hp.y = h1;
    __nv_bfloat162 lp;
    lp.x = __float2bfloat16(v0 - __bfloat162float(h0));
    lp.y = __float2bfloat16(v1 - __bfloat162float(h1));
    *(__nv_bfloat162*)(Ch + (size_t)row * ldc + col) = hp;
    *(__nv_bfloat162*)(Cl + (size_t)row * ldc + col) = lp;
}

template <int EPI>
__global__ __launch_bounds__(256, 1)
void gemm_bf16x3(
    const __nv_bfloat16* __restrict__ Ah, const __nv_bfloat16* __restrict__ Al, int lda,
    const __nv_bfloat16* __restrict__ Bh, const __nv_bfloat16* __restrict__ Bl, int ldb,
    int Kdim,
    float* __restrict__ Cf, __nv_bfloat16* __restrict__ Ch, __nv_bfloat16* __restrict__ Cl,
    int ldc,
    const float* __restrict__ aux1, const float* __restrict__ aux2, int auxld)
{
    extern __shared__ __align__(128) char sm[];
    const uint32_t sbase = smem_u32(sm);
    const int t = threadIdx.x, lane = t & 31, wid = t >> 5;
    const int wm = wid >> 1, wn = wid & 1;   // 4 x 2 warp grid, warp tile 32x32
    const int m0 = blockIdx.y * 128, n0 = blockIdx.x * 64;
    const int nch = Kdim >> 5;

    float acc[2][4][4] = {};   // [mi][nj][4]

#pragma unroll
    for (int c = 0; c < 2; c++) {
        const uint32_t sb = sbase + c * STAGEB;
        issue_tileA(sb + OFF_AH, Ah, lda, m0, c * 32, t);
        issue_tileA(sb + OFF_AL, Al, lda, m0, c * 32, t);
        issue_tileB(sb + OFF_BH, Bh, ldb, n0, c * 32, t);
        issue_tileB(sb + OFF_BL, Bl, ldb, n0, c * 32, t);
        CP_COMMIT();
    }

    const uint32_t a_off = (uint32_t)((lane & 15) * TSTRIDE + (lane >> 4) * 16);
    const uint32_t b_off = (uint32_t)(((lane & 7) + ((lane >> 4) & 1) * 8) * TSTRIDE
                                      + ((lane >> 3) & 1) * 16);

    for (int c = 0; c < nch; c++) {
        CP_WAIT(1);
        __syncthreads();
        if (c + 2 < nch) {
            const uint32_t sb = sbase + ((c + 2) % NSTAGE) * STAGEB;
            issue_tileA(sb + OFF_AH, Ah, lda, m0, (c + 2) * 32, t);
            issue_tileA(sb + OFF_AL, Al, lda, m0, (c + 2) * 32, t);
            issue_tileB(sb + OFF_BH, Bh, ldb, n0, (c + 2) * 32, t);
            issue_tileB(sb + OFF_BL, Bl, ldb, n0, (c + 2) * 32, t);
        }
        CP_COMMIT();

        const uint32_t sb = sbase + (c % NSTAGE) * STAGEB;
        const uint32_t sAh = sb + OFF_AH + wm * 32 * TSTRIDE;
        const uint32_t sAl = sb + OFF_AL + wm * 32 * TSTRIDE;
        const uint32_t sBh = sb + OFF_BH + wn * 32 * TSTRIDE;
        const uint32_t sBl = sb + OFF_BL + wn * 32 * TSTRIDE;

#pragma unroll
        for (int ks = 0; ks < 2; ks++) {
            uint32_t fAh[2][4], fAl[2][4], fBh[4][2], fBl[4][2];
#pragma unroll
            for (int mi = 0; mi < 2; mi++) {
                const uint32_t ao = a_off + mi * 16 * TSTRIDE + ks * 32;
                LDSM4(fAh[mi][0], fAh[mi][1], fAh[mi][2], fAh[mi][3], sAh + ao);
                LDSM4(fAl[mi][0], fAl[mi][1], fAl[mi][2], fAl[mi][3], sAl + ao);
            }
#pragma unroll
            for (int np = 0; np < 2; np++) {
                const uint32_t bo = b_off + np * 16 * TSTRIDE + ks * 32;
                LDSM4(fBh[np*2][0], fBh[np*2][1], fBh[np*2+1][0], fBh[np*2+1][1], sBh + bo);
                LDSM4(fBl[np*2][0], fBl[np*2][1], fBl[np*2+1][0], fBl[np*2+1][1], sBl + bo);
            }
#pragma unroll
            for (int mi = 0; mi < 2; mi++)
#pragma unroll
                for (int nj = 0; nj < 4; nj++) {
                    mma16816(acc[mi][nj], fAh[mi], fBh[nj]);
                    mma16816(acc[mi][nj], fAh[mi], fBl[nj]);
                    mma16816(acc[mi][nj], fAl[mi], fBh[nj]);
                }
        }
    }

    __syncthreads();

    float* smf = (float*)sm;
    if (EPI == EP_M2) {
        if (t < 64) {
            float s = 0.f;
#pragma unroll
            for (int p = 0; p < 8; p++) s += aux2[p * 512 + n0 + t];
            smf[t] = s;
        }
        __syncthreads();
    }

    const int g = lane >> 2, tq = lane & 3;
#pragma unroll
    for (int mi = 0; mi < 2; mi++) {
#pragma unroll
        for (int nj = 0; nj < 4; nj++) {
            const int row = m0 + wm * 32 + mi * 16 + g;
            const int col = n0 + wn * 32 + nj * 8 + tq * 2;
            float v00 = acc[mi][nj][0], v01 = acc[mi][nj][1];
            float v10 = acc[mi][nj][2], v11 = acc[mi][nj][3];
            if (EPI == EP_F32) {
                *(float2*)(Cf + (size_t)row * ldc + col) = make_float2(v00, v01);
                *(float2*)(Cf + (size_t)(row + 8) * ldc + col) = make_float2(v10, v11);
            } else if (EPI == EP_OUT) {
                const float b0 = aux1[col], b1 = aux1[col + 1];
                *(float2*)(Cf + (size_t)row * ldc + col) = make_float2(v00 + b0, v01 + b1);
                *(float2*)(Cf + (size_t)(row + 8) * ldc + col) = make_float2(v10 + b0, v11 + b1);
            } else {
                if (EPI == EP_M2) {
                    const float c0 = smf[col - n0], c1 = smf[col - n0 + 1];
                    const float bm0 = aux1[row], bm8 = aux1[row + 8];
                    v00 = fmaf(bm0, c0, v00); v01 = fmaf(bm0, c1, v01);
                    v10 = fmaf(bm8, c0, v10); v11 = fmaf(bm8, c1, v11);
                } else if (EPI == EP_WEFFT) {
                    v00 += aux1[(size_t)row * auxld + col];
                    v01 += aux1[(size_t)row * auxld + col + 1];
                    v10 += aux1[(size_t)(row + 8) * auxld + col];
                    v11 += aux1[(size_t)(row + 8) * auxld + col + 1];
                }
                store_hilo(Ch, Cl, ldc, row, col, v00, v01);
                store_hilo(Ch, Cl, ldc, row + 8, col, v10, v11);
            }
        }
    }
}

// ---------------- fused conversions ----------------
__device__ __forceinline__ void split4(const float* vv, __nv_bfloat16* dh,
                                       __nv_bfloat16* dl, size_t o) {
#pragma unroll
    for (int x = 0; x < 4; x += 2) {
        __nv_bfloat16 h0 = __float2bfloat16(vv[x]);
        __nv_bfloat16 h1 = __float2bfloat16(vv[x + 1]);
        __nv_bfloat162 hp; hp.x = h0; hp.y = h1;
        __nv_bfloat162 lp;
        lp.x = __float2bfloat16(vv[x] - __bfloat162float(h0));
        lp.y = __float2bfloat16(vv[x + 1] - __bfloat162float(h1));
        *(__nv_bfloat162*)(dh + o + x) = hp;
        *(__nv_bfloat162*)(dl + o + x) = lp;
    }
}

// convA: mention (2048 blks) | Wv (256) | Wu (256)   -- all contiguous
__global__ __launch_bounds__(256) void convA(
    const float* __restrict__ mention, const float* __restrict__ Wv,
    const float* __restrict__ Wu,
    __nv_bfloat16* __restrict__ mhi, __nv_bfloat16* __restrict__ mlo,
    __nv_bfloat16* __restrict__ wvuh, __nv_bfloat16* __restrict__ wvul)
{
    const int blk = blockIdx.x, t = threadIdx.x;
    const float* src; __nv_bfloat16 *dh, *dl; size_t off;
    if (blk < 2048)      { src = mention; dh = mhi; dl = mlo; off = (size_t)blk * 1024; }
    else if (blk < 2304) { src = Wv; dh = wvuh; dl = wvul; off = (size_t)(blk - 2048) * 1024; }
    else                 { src = Wu; dh = wvuh + 256*1024; dl = wvul + 256*1024;
                           off = (size_t)(blk - 2304) * 1024; }
    const size_t i = off + t * 4;
    float4 v = *(const float4*)(src + i);
    split4((const float*)&v, dh, dl, i);
}

// convB: Wr flat (512 blks) | Wo2 strided (512 blks)
__global__ __launch_bounds__(256) void convB(
    const float* __restrict__ Wr, const float* __restrict__ Wo,
    __nv_bfloat16* __restrict__ wrh, __nv_bfloat16* __restrict__ wrl,
    __nv_bfloat16* __restrict__ wo2h, __nv_bfloat16* __restrict__ wo2l)
{
    const int blk = blockIdx.x, t = threadIdx.x;
    if (blk < 512) {
        const size_t i = (size_t)blk * 1024 + t * 4;
        float4 v = *(const float4*)(Wr + i);
        split4((const float*)&v, wrh, wrl, i);
    } else {
        const size_t li = (size_t)(blk - 512) * 1024 + t * 4;
        const int r = (int)(li >> 9), c = (int)(li & 511);
        float4 v = *(const float4*)(Wo + 1024 + (size_t)r * 1536 + c);
        split4((const float*)&v, wo2h, wo2l, (size_t)r * 512 + c);
    }
}

// RM[1024,512] -> RMT[512,1024] hi/lo (tiled transpose)
__global__ __launch_bounds__(256) void convT_hilo(
    const float* __restrict__ RM, __nv_bfloat16* __restrict__ dh, __nv_bfloat16* __restrict__ dl)
{
    __shared__ float tb[32][33];
    const int tx = threadIdx.x, ty = threadIdx.y;
    const int k0 = blockIdx.x * 32, i0 = blockIdx.y * 32;
#pragma unroll
    for (int q = 0; q < 4; q++)
        tb[ty + q * 8][tx] = RM[(size_t)(k0 + ty + q * 8) * 512 + i0 + tx];
    __syncthreads();
#pragma unroll
    for (int q = 0; q < 4; q++) {
        float v = tb[tx][ty + q * 8];
        size_t o = (size_t)(i0 + ty + q * 8) * 1024 + k0 + tx;
        __nv_bfloat16 h = __float2bfloat16(v);
        dh[o] = h;
        dl[o] = __float2bfloat16(v - __bfloat162float(h));
    }
}

// ---------------- score epilogue ----------------
__global__ __launch_bounds__(256) void score_epilogue(
    const float* __restrict__ P, const float* __restrict__ bv,
    const float* __restrict__ bu, const float* __restrict__ Wa,
    const float* __restrict__ ba, float* __restrict__ g)
{
    const int warp = threadIdx.x >> 5, lane = threadIdx.x & 31;
    const int row = blockIdx.x * 8 + warp;
    const float* pr = P + (size_t)row * 512;
    float s = 0.f;
#pragma unroll
    for (int q = 0; q < 8; q++) {
        const int c = lane + q * 32;
        const float v = tanhf(pr[c] + bv[c]);
        float u = pr[256 + c] + bu[c];
        u = 1.f / (1.f + expf(-u));
        s += v * u * Wa[c];
    }
#pragma unroll
    for (int o = 16; o; o >>= 1) s += __shfl_xor_sync(0xffffffffu, s, o);
    if (lane == 0) g[row] = s + ba[0];
}

// ---------------- softmax-pool -> E hi/lo ----------------
__global__ __launch_bounds__(256) void pool2(
    const float* __restrict__ mention, const int* __restrict__ ent,
    const int* __restrict__ msk, const float* __restrict__ g,
    __nv_bfloat16* __restrict__ Eh, __nv_bfloat16* __restrict__ El)
{
    const int be = blockIdx.x, b = be >> 7, tid = threadIdx.x;
    __shared__ float w[16];
    __shared__ int idx[16];
    if (tid < 16) {
        const int id = ent[(size_t)be * 16 + tid];
        idx[tid] = id;
        w[tid] = msk[(size_t)be * 16 + tid] ? g[b * 256 + id] : -1e25f;
    }
    __syncthreads();
    if (tid == 0) {
        float mx = -INFINITY;
#pragma unroll
        for (int k = 0; k < 16; k++) mx = fmaxf(mx, w[k]);
        float e[16], sum = 0.f;
#pragma unroll
        for (int k = 0; k < 16; k++) { e[k] = expf(w[k] - mx); sum += e[k]; }
        const float inv = 1.f / sum;
#pragma unroll
        for (int k = 0; k < 16; k++) w[k] = e[k] * inv;
    }
    __syncthreads();
    const float* mb = mention + (size_t)b * 256 * 1024;
    const int h0 = tid * 4;
    float4 acc = make_float4(0.f, 0.f, 0.f, 0.f);
#pragma unroll
    for (int k = 0; k < 16; k++) {
        const float4 v = *(const float4*)(mb + (size_t)idx[k] * 1024 + h0);
        const float wk = w[k];
        acc.x = fmaf(wk, v.x, acc.x);
        acc.y = fmaf(wk, v.y, acc.y);
        acc.z = fmaf(wk, v.z, acc.z);
        acc.w = fmaf(wk, v.w, acc.w);
    }
    split4((const float*)&acc, Eh, El, (size_t)be * 1024 + h0);
}

// ---------------- colsum partials of RM ----------------
__global__ __launch_bounds__(512) void colsum_part(
    const float* __restrict__ RM, float* __restrict__ part)
{
    const int j = threadIdx.x;
    const int p = blockIdx.x;
    float s = 0.f;
#pragma unroll 4
    for (int r = 0; r < 128; r++) s += RM[(size_t)(p * 128 + r) * 512 + j];
    part[p * 512 + j] = s;
}

// ---------------- launch ----------------
extern "C" void kernel_launch(void* const* d_in, const int* in_sizes, int n_in,
                              void* d_out, int out_size)
{
    const float* mention  = (const float*)d_in[0];
    const int*   entities = (const int*)d_in[1];
    const int*   masks    = (const int*)d_in[2];
    const float* RM       = (const float*)d_in[3];
    const float* Wv       = (const float*)d_in[4];
    const float* bv       = (const float*)d_in[5];
    const float* Wu       = (const float*)d_in[6];
    const float* bu       = (const float*)d_in[7];
    const float* Wa       = (const float*)d_in[8];
    const float* ba       = (const float*)d_in[9];
    const float* Wr       = (const float*)d_in[10];
    const float* br       = (const float*)d_in[11];
    const float* Wo       = (const float*)d_in[12];
    const float* bo       = (const float*)d_in[13];
    float* out = (float*)d_out;

    __nv_bfloat16 *mhi, *mlo, *wvuh, *wvul, *rmth, *rmtl, *wrh, *wrl, *wo2h, *wo2l;
    __nv_bfloat16 *cgh, *cgl, *m2h, *m2l, *wth, *wtl, *eh, *el;
    float *P, *score, *part;
    cudaGetSymbolAddress((void**)&mhi, g_mhi);   cudaGetSymbolAddress((void**)&mlo, g_mlo);
    cudaGetSymbolAddress((void**)&wvuh, g_wvuh); cudaGetSymbolAddress((void**)&wvul, g_wvul);
    cudaGetSymbolAddress((void**)&rmth, g_rmth); cudaGetSymbolAddress((void**)&rmtl, g_rmtl);
    cudaGetSymbolAddress((void**)&wrh, g_wrh);   cudaGetSymbolAddress((void**)&wrl, g_wrl);
    cudaGetSymbolAddress((void**)&wo2h, g_wo2h); cudaGetSymbolAddress((void**)&wo2l, g_wo2l);
    cudaGetSymbolAddress((void**)&cgh, g_cgh);   cudaGetSymbolAddress((void**)&cgl, g_cgl);
    cudaGetSymbolAddress((void**)&m2h, g_m2h);   cudaGetSymbolAddress((void**)&m2l, g_m2l);
    cudaGetSymbolAddress((void**)&wth, g_wth);   cudaGetSymbolAddress((void**)&wtl, g_wtl);
    cudaGetSymbolAddress((void**)&eh, g_eh);     cudaGetSymbolAddress((void**)&el, g_el);
    cudaGetSymbolAddress((void**)&P, g_P);
    cudaGetSymbolAddress((void**)&score, g_score);
    cudaGetSymbolAddress((void**)&part, g_part);

    cudaFuncSetAttribute(gemm_bf16x3<EP_F32>,   cudaFuncAttributeMaxDynamicSharedMemorySize, SMEM_GEMM);
    cudaFuncSetAttribute(gemm_bf16x3<EP_HILO>,  cudaFuncAttributeMaxDynamicSharedMemorySize, SMEM_GEMM);
    cudaFuncSetAttribute(gemm_bf16x3<EP_M2>,    cudaFuncAttributeMaxDynamicSharedMemorySize, SMEM_GEMM);
    cudaFuncSetAttribute(gemm_bf16x3<EP_WEFFT>, cudaFuncAttributeMaxDynamicSharedMemorySize, SMEM_GEMM);
    cudaFuncSetAttribute(gemm_bf16x3<EP_OUT>,   cudaFuncAttributeMaxDynamicSharedMemorySize, SMEM_GEMM);

    // fork: relation chain on s_rel
    cudaEventRecord(e_fork, 0);
    cudaStreamWaitEvent(s_rel, e_fork, 0);

    // ---- relation chain (s_rel) ----
    convB<<<1024, 256, 0, s_rel>>>(Wr, Wo, wrh, wrl, wo2h, wo2l);
    convT_hilo<<<dim3(32, 16), dim3(32, 8), 0, s_rel>>>(RM, rmth, rmtl);
    colsum_part<<<8, 512, 0, s_rel>>>(RM, part);
    // Cg = RMT @ RMT^T  [512,512]
    gemm_bf16x3<EP_HILO><<<dim3(8, 4), 256, SMEM_GEMM, s_rel>>>(
        rmth, rmtl, 1024, rmth, rmtl, 1024, 1024, nullptr, cgh, cgl, 512,
        nullptr, nullptr, 0);
    // M2 = Wr @ Cg^T + br (x) colsum   (Cg symmetric)
    gemm_bf16x3<EP_M2><<<dim3(8, 8), 256, SMEM_GEMM, s_rel>>>(
        wrh, wrl, 512, cgh, cgl, 512, 512, nullptr, m2h, m2l, 512,
        br, part, 0);
    // WT = Wo2 @ M2^T + Wo1  [1024,1024]
    gemm_bf16x3<EP_WEFFT><<<dim3(16, 8), 256, SMEM_GEMM, s_rel>>>(
        wo2h, wo2l, 512, m2h, m2l, 512, 512, nullptr, wth, wtl, 1024,
        Wo, nullptr, 1536);
    cudaEventRecord(e_rel, s_rel);

    // ---- attention chain (legacy stream) ----
    convA<<<2560, 256>>>(mention, Wv, Wu, mhi, mlo, wvuh, wvul);
    // P = mention @ Wvu^T  [2048,512]
    gemm_bf16x3<EP_F32><<<dim3(8, 16), 256, SMEM_GEMM>>>(
        mhi, mlo, 1024, wvuh, wvul, 1024, 1024, P, nullptr, nullptr, 512,
        nullptr, nullptr, 0);
    score_epilogue<<<256, 256>>>(P, bv, bu, Wa, ba, score);
    pool2<<<1024, 256>>>(mention, entities, masks, score, eh, el);

    // join, then out = E @ WT^T + bo  [1024,1024]
    cudaStreamWaitEvent(0, e_rel, 0);
    gemm_bf16x3<EP_OUT><<<dim3(16, 8), 256, SMEM_GEMM>>>(
        eh, el, 1024, wth, wtl, 1024, 1024, out, nullptr, nullptr, 1024,
        bo, nullptr, 0);
}

// round 5
// speedup vs baseline: 3.6170x; 1.1811x over previous
#include <cuda_runtime.h>
#include <cuda_bf16.h>
#include <stdint.h>
#include <math.h>

// ============================================================================
// Shapes: B=8, M=256, E=128, K=16, H=1024, A=256, R=1024, RMS=512
//   P = mention @ Wvu^T (Wv/Wu rows interleaved), score fused into epilogue
//   E = softmax-pooled mention rows
//   Cg = RMT@RMT^T (split-K4) ; M2 = Wr Cg + br(x)colsum (split-K2)
//   WT = Wo2 M2^T + Wo1 ; out = E WT^T + bo
// GEMMs: C = A[M,K]*B[N,K]^T via mma.m16n8k16.bf16, bf16x3 hi/lo split.
// Block tile 128x64, BK=32, 8 warps (4x2), 3-stage cp.async.
// ============================================================================

__device__ __nv_bfloat16 g_mhi[2048*1024], g_mlo[2048*1024];
__device__ __nv_bfloat16 g_wvuh[512*1024], g_wvul[512*1024];   // interleaved v/u rows
__device__ __nv_bfloat16 g_rmth[512*1024], g_rmtl[512*1024];
__device__ __nv_bfloat16 g_wrh[1024*512],  g_wrl[1024*512];
__device__ __nv_bfloat16 g_wo2h[1024*512], g_wo2l[1024*512];
__device__ __nv_bfloat16 g_cgh[512*512],   g_cgl[512*512];
__device__ __nv_bfloat16 g_m2h[1024*512],  g_m2l[1024*512];
__device__ __nv_bfloat16 g_wth[1024*1024], g_wtl[1024*1024];
__device__ __nv_bfloat16 g_eh[1024*1024],  g_el[1024*1024];
__device__ float g_P[2048*512];      // split-K partial arena (reused)
__device__ float g_g16[16*2048];     // score column-block partials
__device__ float g_part[8*512];

static cudaStream_t s_rel;
static cudaEvent_t  e_fork, e_rel;
static struct StreamInit {
    StreamInit() {
        cudaStreamCreateWithFlags(&s_rel, cudaStreamNonBlocking);
        cudaEventCreateWithFlags(&e_fork, cudaEventDisableTiming);
        cudaEventCreateWithFlags(&e_rel,  cudaEventDisableTiming);
    }
} s_init;

__device__ __forceinline__ uint32_t smem_u32(const void* p) {
    uint32_t a;
    asm("{ .reg .u64 t; cvta.to.shared.u64 t, %1; cvt.u32.u64 %0, t; }" : "=r"(a) : "l"(p));
    return a;
}

#define CP16(dst, src) \
    asm volatile("cp.async.cg.shared.global [%0], [%1], 16;" :: "r"(dst), "l"(src))
#define CP_COMMIT() asm volatile("cp.async.commit_group;" ::: "memory")
#define CP_WAIT(n)  asm volatile("cp.async.wait_group %0;" :: "n"(n) : "memory")

#define LDSM4(r0, r1, r2, r3, addr) \
    asm volatile("ldmatrix.sync.aligned.m8n8.x4.shared.b16 {%0,%1,%2,%3}, [%4];" \
        : "=r"(r0), "=r"(r1), "=r"(r2), "=r"(r3) : "r"(addr))

__device__ __forceinline__ void mma16816(float* c, const uint32_t* a, const uint32_t* b) {
    asm volatile("mma.sync.aligned.m16n8k16.row.col.f32.bf16.bf16.f32 "
        "{%0,%1,%2,%3}, {%4,%5,%6,%7}, {%8,%9}, {%0,%1,%2,%3};"
        : "+f"(c[0]), "+f"(c[1]), "+f"(c[2]), "+f"(c[3])
        : "r"(a[0]), "r"(a[1]), "r"(a[2]), "r"(a[3]), "r"(b[0]), "r"(b[1]));
}

#define TSTRIDE 80
#define ATILEB  (128 * TSTRIDE)
#define BTILEB  (64 * TSTRIDE)
#define STAGEB  (2 * ATILEB + 2 * BTILEB)
#define NSTAGE  3
#define SMEM_GEMM (NSTAGE * STAGEB)

#define OFF_AH 0
#define OFF_AL ATILEB
#define OFF_BH (2 * ATILEB)
#define OFF_BL (2 * ATILEB + BTILEB)

enum { EP_SCORE = 0, EP_PART = 1, EP_WEFFT = 2, EP_OUT = 3 };

__device__ __forceinline__ void issue_tileA(uint32_t sdst,
        const __nv_bfloat16* __restrict__ G, int ld, int r0, int k0, int t) {
#pragma unroll
    for (int q = 0; q < 2; q++) {
        const int idx = t + (q << 8);
        const int r = idx >> 2, ch = idx & 3;
        CP16(sdst + r * TSTRIDE + ch * 16,
             G + (size_t)(r0 + r) * ld + k0 + ch * 8);
    }
}
__device__ __forceinline__ void issue_tileB(uint32_t sdst,
        const __nv_bfloat16* __restrict__ G, int ld, int r0, int k0, int t) {
    const int r = t >> 2, ch = t & 3;
    CP16(sdst + r * TSTRIDE + ch * 16,
         G + (size_t)(r0 + r) * ld + k0 + ch * 8);
}

__device__ __forceinline__ void store_hilo(__nv_bfloat16* Ch, __nv_bfloat16* Cl,
        int ldc, int row, int col, float v0, float v1) {
    __nv_bfloat16 h0 = __float2bfloat16(v0);
    __nv_bfloat16 h1 = __float2bfloat16(v1);
    __nv_bfloat162 hp; hp.x = h0; hp.y = h1;
    __nv_bfloat162 lp;
    lp.x = __float2bfloat16(v0 - __bfloat162float(h0));
    lp.y = __float2bfloat16(v1 - __bfloat162float(h1));
    *(__nv_bfloat162*)(Ch + (size_t)row * ldc + col) = hp;
    *(__nv_bfloat162*)(Cl + (size_t)row * ldc + col) = lp;
}

template <int EPI>
__global__ __launch_bounds__(256, 1)
void gemm_bf16x3(
    const __nv_bfloat16* __restrict__ Ah, const __nv_bfloat16* __restrict__ Al, int lda,
    const __nv_bfloat16* __restrict__ Bh, const __nv_bfloat16* __restrict__ Bl, int ldb,
    int Kper,
    float* __restrict__ Cf, __nv_bfloat16* __restrict__ Ch, __nv_bfloat16* __restrict__ Cl,
    int ldc,
    const float* __restrict__ aux1, const float* __restrict__ aux2,
    const float* __restrict__ aux3, int auxld, size_t partStride)
{
    extern __shared__ __align__(128) char sm[];
    const uint32_t sbase = smem_u32(sm);
    const int t = threadIdx.x, lane = t & 31, wid = t >> 5;
    const int wm = wid >> 1, wn = wid & 1;
    const int m0 = blockIdx.y * 128, n0 = blockIdx.x * 64;
    const int Koff = blockIdx.z * Kper;
    const int nch = Kper >> 5;

    float acc[2][4][4] = {};

#pragma unroll
    for (int c = 0; c < 2; c++) {
        const uint32_t sb = sbase + c * STAGEB;
        issue_tileA(sb + OFF_AH, Ah, lda, m0, Koff + c * 32, t);
        issue_tileA(sb + OFF_AL, Al, lda, m0, Koff + c * 32, t);
        issue_tileB(sb + OFF_BH, Bh, ldb, n0, Koff + c * 32, t);
        issue_tileB(sb + OFF_BL, Bl, ldb, n0, Koff + c * 32, t);
        CP_COMMIT();
    }

    const uint32_t a_off = (uint32_t)((lane & 15) * TSTRIDE + (lane >> 4) * 16);
    const uint32_t b_off = (uint32_t)(((lane & 7) + ((lane >> 4) & 1) * 8) * TSTRIDE
                                      + ((lane >> 3) & 1) * 16);

    for (int c = 0; c < nch; c++) {
        CP_WAIT(1);
        __syncthreads();
        if (c + 2 < nch) {
            const uint32_t sb = sbase + ((c + 2) % NSTAGE) * STAGEB;
            issue_tileA(sb + OFF_AH, Ah, lda, m0, Koff + (c + 2) * 32, t);
            issue_tileA(sb + OFF_AL, Al, lda, m0, Koff + (c + 2) * 32, t);
            issue_tileB(sb + OFF_BH, Bh, ldb, n0, Koff + (c + 2) * 32, t);
            issue_tileB(sb + OFF_BL, Bl, ldb, n0, Koff + (c + 2) * 32, t);
        }
        CP_COMMIT();

        const uint32_t sb = sbase + (c % NSTAGE) * STAGEB;
        const uint32_t sAh = sb + OFF_AH + wm * 32 * TSTRIDE;
        const uint32_t sAl = sb + OFF_AL + wm * 32 * TSTRIDE;
        const uint32_t sBh = sb + OFF_BH + wn * 32 * TSTRIDE;
        const uint32_t sBl = sb + OFF_BL + wn * 32 * TSTRIDE;

#pragma unroll
        for (int ks = 0; ks < 2; ks++) {
            uint32_t fAh[2][4], fAl[2][4], fBh[4][2], fBl[4][2];
#pragma unroll
            for (int mi = 0; mi < 2; mi++) {
                const uint32_t ao = a_off + mi * 16 * TSTRIDE + ks * 32;
                LDSM4(fAh[mi][0], fAh[mi][1], fAh[mi][2], fAh[mi][3], sAh + ao);
                LDSM4(fAl[mi][0], fAl[mi][1], fAl[mi][2], fAl[mi][3], sAl + ao);
            }
#pragma unroll
            for (int np = 0; np < 2; np++) {
                const uint32_t bo = b_off + np * 16 * TSTRIDE + ks * 32;
                LDSM4(fBh[np*2][0], fBh[np*2][1], fBh[np*2+1][0], fBh[np*2+1][1], sBh + bo);
                LDSM4(fBl[np*2][0], fBl[np*2][1], fBl[np*2+1][0], fBl[np*2+1][1], sBl + bo);
            }
#pragma unroll
            for (int mi = 0; mi < 2; mi++)
#pragma unroll
                for (int nj = 0; nj < 4; nj++) {
                    mma16816(acc[mi][nj], fAh[mi], fBh[nj]);
                    mma16816(acc[mi][nj], fAh[mi], fBl[nj]);
                    mma16816(acc[mi][nj], fAl[mi], fBh[nj]);
                }
        }
    }

    __syncthreads();

    const int g = lane >> 2, tq = lane & 3;

    if (EPI == EP_SCORE) {
        // cols interleaved [v|u] pairs: a = global_col/2
        // per (mi): partial over this warp's 32 cols for rows r and r+8
        float pl[2];
#pragma unroll
        for (int mi = 0; mi < 2; mi++) {
            float p0 = 0.f, p8 = 0.f;
#pragma unroll
            for (int nj = 0; nj < 4; nj++) {
                const int C = n0 + wn * 32 + nj * 8 + tq * 2;
                const int a = C >> 1;
                const float bva = aux1[a], bua = aux2[a], waa = aux3[a];
                {
                    float v = tanhf(acc[mi][nj][0] + bva);
                    float u = acc[mi][nj][1] + bua;
                    u = 1.f / (1.f + __expf(-u));
                    p0 = fmaf(v * u, waa, p0);
                }
                {
                    float v = tanhf(acc[mi][nj][2] + bva);
                    float u = acc[mi][nj][3] + bua;
                    u = 1.f / (1.f + __expf(-u));
                    p8 = fmaf(v * u, waa, p8);
                }
            }
            pl[0] = p0; pl[1] = p8;
#pragma unroll
            for (int o = 1; o <= 2; o <<= 1) {
                pl[0] += __shfl_xor_sync(0xffffffffu, pl[0], o);
                pl[1] += __shfl_xor_sync(0xffffffffu, pl[1], o);
            }
            if (tq == 0) {
                const int cb = blockIdx.x * 2 + wn;
                const int row = m0 + wm * 32 + mi * 16 + g;
                Cf[(size_t)cb * 2048 + row] = pl[0];
                Cf[(size_t)cb * 2048 + row + 8] = pl[1];
            }
        }
        return;
    }

#pragma unroll
    for (int mi = 0; mi < 2; mi++) {
#pragma unroll
        for (int nj = 0; nj < 4; nj++) {
            const int row = m0 + wm * 32 + mi * 16 + g;
            const int col = n0 + wn * 32 + nj * 8 + tq * 2;
            float v00 = acc[mi][nj][0], v01 = acc[mi][nj][1];
            float v10 = acc[mi][nj][2], v11 = acc[mi][nj][3];
            if (EPI == EP_PART) {
                float* dst = Cf + blockIdx.z * partStride;
                *(float2*)(dst + (size_t)row * ldc + col) = make_float2(v00, v01);
                *(float2*)(dst + (size_t)(row + 8) * ldc + col) = make_float2(v10, v11);
            } else if (EPI == EP_OUT) {
                const float b0 = aux1[col], b1 = aux1[col + 1];
                *(float2*)(Cf + (size_t)row * ldc + col) = make_float2(v00 + b0, v01 + b1);
                *(float2*)(Cf + (size_t)(row + 8) * ldc + col) = make_float2(v10 + b0, v11 + b1);
            } else {  // EP_WEFFT
                v00 += aux1[(size_t)row * auxld + col];
                v01 += aux1[(size_t)row * auxld + col + 1];
                v10 += aux1[(size_t)(row + 8) * auxld + col];
                v11 += aux1[(size_t)(row + 8) * auxld + col + 1];
                store_hilo(Ch, Cl, ldc, row, col, v00, v01);
                store_hilo(Ch, Cl, ldc, row + 8, col, v10, v11);
            }
        }
    }
}

// ---------------- helpers ----------------
__device__ __forceinline__ void split4(const float* vv, __nv_bfloat16* dh,
                                       __nv_bfloat16* dl, size_t o) {
#pragma unroll
    for (int x = 0; x < 4; x += 2) {
        __nv_bfloat16 h0 = __float2bfloat16(vv[x]);
        __nv_bfloat16 h1 = __float2bfloat16(vv[x + 1]);
        __nv_bfloat162 hp; hp.x = h0; hp.y = h1;
        __nv_bfloat162 lp;
        lp.x = __float2bfloat16(vv[x] - __bfloat162float(h0));
        lp.y = __float2bfloat16(vv[x + 1] - __bfloat162float(h1));
        *(__nv_bfloat162*)(dh + o + x) = hp;
        *(__nv_bfloat162*)(dl + o + x) = lp;
    }
}

// fuse_cg: cg = sum of 4 split-K partials -> hi/lo   [512x512]
__global__ __launch_bounds__(256) void fuse_cg(
    const float* __restrict__ p, __nv_bfloat16* __restrict__ ch, __nv_bfloat16* __restrict__ cl)
{
    const size_t base = ((size_t)blockIdx.x * 256 + threadIdx.x) * 4;
    float4 s = *(const float4*)(p + base);
#pragma unroll
    for (int z = 1; z < 4; z++) {
        const float4 q = *(const float4*)(p + (size_t)z * 262144 + base);
        s.x += q.x; s.y += q.y; s.z += q.z; s.w += q.w;
    }
    split4((const float*)&s, ch, cl, base);
}

// fuse_m2: m2 = p0+p1 + br[m]*colsum[n] -> hi/lo   [1024x512]
__global__ __launch_bounds__(256) void fuse_m2(
    const float* __restrict__ p, const float* __restrict__ part,
    const float* __restrict__ br,
    __nv_bfloat16* __restrict__ mh, __nv_bfloat16* __restrict__ ml)
{
    const size_t base = ((size_t)blockIdx.x * 256 + threadIdx.x) * 4;
    const int n = (int)(base & 511), m = (int)(base >> 9);
    float4 s = *(const float4*)(p + base);
    const float4 q = *(const float4*)(p + 524288 + base);
    float sv[4] = {s.x + q.x, s.y + q.y, s.z + q.z, s.w + q.w};
    const float bm = br[m];
#pragma unroll
    for (int x = 0; x < 4; x++) {
        float cs = 0.f;
#pragma unroll
        for (int pp = 0; pp < 8; pp++) cs += part[pp * 512 + n + x];
        sv[x] = fmaf(bm, cs, sv[x]);
    }
    split4(sv, mh, ml, base);
}

// convA: mention (2048 blks) | Wv -> interleaved even rows | Wu -> odd rows
__global__ __launch_bounds__(256) void convA(
    const float* __restrict__ mention, const float* __restrict__ Wv,
    const float* __restrict__ Wu,
    __nv_bfloat16* __restrict__ mhi, __nv_bfloat16* __restrict__ mlo,
    __nv_bfloat16* __restrict__ wvuh, __nv_bfloat16* __restrict__ wvul)
{
    const int blk = blockIdx.x, t = threadIdx.x;
    if (blk < 2048) {
        const size_t i = (size_t)blk * 1024 + t * 4;
        float4 v = *(const float4*)(mention + i);
        split4((const float*)&v, mhi, mlo, i);
    } else if (blk < 2304) {
        const int r = blk - 2048;
        const size_t si = (size_t)r * 1024 + t * 4;
        float4 v = *(const float4*)(Wv + si);
        split4((const float*)&v, wvuh, wvul, (size_t)(2 * r) * 1024 + t * 4);
    } else {
        const int r = blk - 2304;
        const size_t si = (size_t)r * 1024 + t * 4;
        float4 v = *(const float4*)(Wu + si);
        split4((const float*)&v, wvuh, wvul, (size_t)(2 * r + 1) * 1024 + t * 4);
    }
}

// convB: Wr flat (512 blks) | Wo2 strided (512 blks)
__global__ __launch_bounds__(256) void convB(
    const float* __restrict__ Wr, const float* __restrict__ Wo,
    __nv_bfloat16* __restrict__ wrh, __nv_bfloat16* __restrict__ wrl,
    __nv_bfloat16* __restrict__ wo2h, __nv_bfloat16* __restrict__ wo2l)
{
    const int blk = blockIdx.x, t = threadIdx.x;
    if (blk < 512) {
        const size_t i = (size_t)blk * 1024 + t * 4;
        float4 v = *(const float4*)(Wr + i);
        split4((const float*)&v, wrh, wrl, i);
    } else {
        const size_t li = (size_t)(blk - 512) * 1024 + t * 4;
        const int r = (int)(li >> 9), c = (int)(li & 511);
        float4 v = *(const float4*)(Wo + 1024 + (size_t)r * 1536 + c);
        split4((const float*)&v, wo2h, wo2l, (size_t)r * 512 + c);
    }
}

__global__ __launch_bounds__(256) void convT_hilo(
    const float* __restrict__ RM, __nv_bfloat16* __restrict__ dh, __nv_bfloat16* __restrict__ dl)
{
    __shared__ float tb[32][33];
    const int tx = threadIdx.x, ty = threadIdx.y;
    const int k0 = blockIdx.x * 32, i0 = blockIdx.y * 32;
#pragma unroll
    for (int q = 0; q < 4; q++)
        tb[ty + q * 8][tx] = RM[(size_t)(k0 + ty + q * 8) * 512 + i0 + tx];
    __syncthreads();
#pragma unroll
    for (int q = 0; q < 4; q++) {
        float v = tb[tx][ty + q * 8];
        size_t o = (size_t)(i0 + ty + q * 8) * 1024 + k0 + tx;
        __nv_bfloat16 h = __float2bfloat16(v);
        dh[o] = h;
        dl[o] = __float2bfloat16(v - __bfloat162float(h));
    }
}

// pool2: masked softmax over K=16 + weighted pooling; g from 16 partials
__global__ __launch_bounds__(256) void pool2(
    const float* __restrict__ mention, const int* __restrict__ ent,
    const int* __restrict__ msk, const float* __restrict__ g16,
    const float* __restrict__ ba,
    __nv_bfloat16* __restrict__ Eh, __nv_bfloat16* __restrict__ El)
{
    const int be = blockIdx.x, b = be >> 7, tid = threadIdx.x;
    __shared__ float w[16];
    __shared__ int idx[16];
    if (tid < 16) {
        const int id = ent[(size_t)be * 16 + tid];
        idx[tid] = id;
        if (msk[(size_t)be * 16 + tid]) {
            float gs = ba[0];
            const int row = b * 256 + id;
#pragma unroll
            for (int cb = 0; cb < 16; cb++) gs += g16[cb * 2048 + row];
            w[tid] = gs;
        } else {
            w[tid] = -1e25f;
        }
    }
    __syncthreads();
    if (tid == 0) {
        float mx = -INFINITY;
#pragma unroll
        for (int k = 0; k < 16; k++) mx = fmaxf(mx, w[k]);
        float e[16], sum = 0.f;
#pragma unroll
        for (int k = 0; k < 16; k++) { e[k] = expf(w[k] - mx); sum += e[k]; }
        const float inv = 1.f / sum;
#pragma unroll
        for (int k = 0; k < 16; k++) w[k] = e[k] * inv;
    }
    __syncthreads();
    const float* mb = mention + (size_t)b * 256 * 1024;
    const int h0 = tid * 4;
    float4 acc = make_float4(0.f, 0.f, 0.f, 0.f);
#pragma unroll
    for (int k = 0; k < 16; k++) {
        const float4 v = *(const float4*)(mb + (size_t)idx[k] * 1024 + h0);
        const float wk = w[k];
        acc.x = fmaf(wk, v.x, acc.x);
        acc.y = fmaf(wk, v.y, acc.y);
        acc.z = fmaf(wk, v.z, acc.z);
        acc.w = fmaf(wk, v.w, acc.w);
    }
    split4((const float*)&acc, Eh, El, (size_t)be * 1024 + h0);
}

__global__ __launch_bounds__(512) void colsum_part(
    const float* __restrict__ RM, float* __restrict__ part)
{
    const int j = threadIdx.x;
    const int p = blockIdx.x;
    float s = 0.f;
#pragma unroll 4
    for (int r = 0; r < 128; r++) s += RM[(size_t)(p * 128 + r) * 512 + j];
    part[p * 512 + j] = s;
}

// ---------------- launch ----------------
extern "C" void kernel_launch(void* const* d_in, const int* in_sizes, int n_in,
                              void* d_out, int out_size)
{
    const float* mention  = (const float*)d_in[0];
    const int*   entities = (const int*)d_in[1];
    const int*   masks    = (const int*)d_in[2];
    const float* RM       = (const float*)d_in[3];
    const float* Wv       = (const float*)d_in[4];
    const float* bv       = (const float*)d_in[5];
    const float* Wu       = (const float*)d_in[6];
    const float* bu       = (const float*)d_in[7];
    const float* Wa       = (const float*)d_in[8];
    const float* ba       = (const float*)d_in[9];
    const float* Wr       = (const float*)d_in[10];
    const float* br       = (const float*)d_in[11];
    const float* Wo       = (const float*)d_in[12];
    const float* bo       = (const float*)d_in[13];
    float* out = (float*)d_out;

    __nv_bfloat16 *mhi, *mlo, *wvuh, *wvul, *rmth, *rmtl, *wrh, *wrl, *wo2h, *wo2l;
    __nv_bfloat16 *cgh, *cgl, *m2h, *m2l, *wth, *wtl, *eh, *el;
    float *parena, *g16, *part;
    cudaGetSymbolAddress((void**)&mhi, g_mhi);   cudaGetSymbolAddress((void**)&mlo, g_mlo);
    cudaGetSymbolAddress((void**)&wvuh, g_wvuh); cudaGetSymbolAddress((void**)&wvul, g_wvul);
    cudaGetSymbolAddress((void**)&rmth, g_rmth); cudaGetSymbolAddress((void**)&rmtl, g_rmtl);
    cudaGetSymbolAddress((void**)&wrh, g_wrh);   cudaGetSymbolAddress((void**)&wrl, g_wrl);
    cudaGetSymbolAddress((void**)&wo2h, g_wo2h); cudaGetSymbolAddress((void**)&wo2l, g_wo2l);
    cudaGetSymbolAddress((void**)&cgh, g_cgh);   cudaGetSymbolAddress((void**)&cgl, g_cgl);
    cudaGetSymbolAddress((void**)&m2h, g_m2h);   cudaGetSymbolAddress((void**)&m2l, g_m2l);
    cudaGetSymbolAddress((void**)&wth, g_wth);   cudaGetSymbolAddress((void**)&wtl, g_wtl);
    cudaGetSymbolAddress((void**)&eh, g_eh);     cudaGetSymbolAddress((void**)&el, g_el);
    cudaGetSymbolAddress((void**)&parena, g_P);
    cudaGetSymbolAddress((void**)&g16, g_g16);
    cudaGetSymbolAddress((void**)&part, g_part);

    cudaFuncSetAttribute(gemm_bf16x3<EP_SCORE>, cudaFuncAttributeMaxDynamicSharedMemorySize, SMEM_GEMM);
    cudaFuncSetAttribute(gemm_bf16x3<EP_PART>,  cudaFuncAttributeMaxDynamicSharedMemorySize, SMEM_GEMM);
    cudaFuncSetAttribute(gemm_bf16x3<EP_WEFFT>, cudaFuncAttributeMaxDynamicSharedMemorySize, SMEM_GEMM);
    cudaFuncSetAttribute(gemm_bf16x3<EP_OUT>,   cudaFuncAttributeMaxDynamicSharedMemorySize, SMEM_GEMM);

    cudaEventRecord(e_fork, 0);
    cudaStreamWaitEvent(s_rel, e_fork, 0);

    // ---- relation chain (s_rel) ----
    convB<<<1024, 256, 0, s_rel>>>(Wr, Wo, wrh, wrl, wo2h, wo2l);
    convT_hilo<<<dim3(32, 16), dim3(32, 8), 0, s_rel>>>(RM, rmth, rmtl);
    colsum_part<<<8, 512, 0, s_rel>>>(RM, part);
    // Cg partials: split-K4, 128 blocks
    gemm_bf16x3<EP_PART><<<dim3(8, 4, 4), 256, SMEM_GEMM, s_rel>>>(
        rmth, rmtl, 1024, rmth, rmtl, 1024, 256, parena, nullptr, nullptr, 512,
        nullptr, nullptr, nullptr, 0, (size_t)512 * 512);
    fuse_cg<<<256, 256, 0, s_rel>>>(parena, cgh, cgl);
    // M2 partials: split-K2, 128 blocks  (Cg symmetric -> use as B)
    gemm_bf16x3<EP_PART><<<dim3(8, 8, 2), 256, SMEM_GEMM, s_rel>>>(
        wrh, wrl, 512, cgh, cgl, 512, 256, parena, nullptr, nullptr, 512,
        nullptr, nullptr, nullptr, 0, (size_t)1024 * 512);
    fuse_m2<<<512, 256, 0, s_rel>>>(parena, part, br, m2h, m2l);
    // WT = Wo2 @ M2^T + Wo1
    gemm_bf16x3<EP_WEFFT><<<dim3(16, 8), 256, SMEM_GEMM, s_rel>>>(
        wo2h, wo2l, 512, m2h, m2l, 512, 512, nullptr, wth, wtl, 1024,
        Wo, nullptr, nullptr, 1536, 0);
    cudaEventRecord(e_rel, s_rel);

    // ---- attention chain (legacy stream) ----
    convA<<<2560, 256>>>(mention, Wv, Wu, mhi, mlo, wvuh, wvul);
    // P with fused score epilogue -> g16 partials
    gemm_bf16x3<EP_SCORE><<<dim3(8, 16), 256, SMEM_GEMM>>>(
        mhi, mlo, 1024, wvuh, wvul, 1024, 1024, g16, nullptr, nullptr, 0,
        bv, bu, Wa, 0, 0);
    pool2<<<1024, 256>>>(mention, entities, masks, g16, ba, eh, el);

    // join, then out = E @ WT^T + bo
    cudaStreamWaitEvent(0, e_rel, 0);
    gemm_bf16x3<EP_OUT><<<dim3(16, 8), 256, SMEM_GEMM>>>(
        eh, el, 1024, wth, wtl, 1024, 1024, out, nullptr, nullptr, 1024,
        bo, nullptr, nullptr, 0, 0);
}

// round 6
// speedup vs baseline: 3.8918x; 1.0760x over previous
#include <cuda_runtime.h>
#include <cuda_bf16.h>
#include <stdint.h>
#include <math.h>

// ============================================================================
// Shapes: B=8, M=256, E=128, K=16, H=1024, A=256, R=1024, RMS=512
//   P = mention @ Wvu^T (Wv/Wu rows interleaved), score fused into epilogue
//   E = softmax-pooled mention rows
//   Cg = RMT@RMT^T (split-K4) ; M2 = Wr Cg + br(x)colsum (split-K2)
//   WT = Wo2 M2^T + Wo1 ; out = E WT^T + bo
// GEMMs: C = A[M,K]*B[N,K]^T via mma.m16n8k16.bf16, bf16x3 hi/lo split.
// Block 128x64, BK=64, 8 warps (4x2), 3-stage cp.async, reg-double-buffered
// ldmatrix fragments.
// ============================================================================

__device__ __nv_bfloat16 g_mhi[2048*1024], g_mlo[2048*1024];
__device__ __nv_bfloat16 g_wvuh[512*1024], g_wvul[512*1024];   // interleaved v/u rows
__device__ __nv_bfloat16 g_rmth[512*1024], g_rmtl[512*1024];
__device__ __nv_bfloat16 g_wrh[1024*512],  g_wrl[1024*512];
__device__ __nv_bfloat16 g_wo2h[1024*512], g_wo2l[1024*512];
__device__ __nv_bfloat16 g_cgh[512*512],   g_cgl[512*512];
__device__ __nv_bfloat16 g_m2h[1024*512],  g_m2l[1024*512];
__device__ __nv_bfloat16 g_wth[1024*1024], g_wtl[1024*1024];
__device__ __nv_bfloat16 g_eh[1024*1024],  g_el[1024*1024];
__device__ float g_P[2048*512];      // split-K partial arena
__device__ float g_g16[16*2048];     // score column-block partials
__device__ float g_part[8*512];

static cudaStream_t s_rel;
static cudaEvent_t  e_fork, e_rel;
static struct StreamInit {
    StreamInit() {
        cudaStreamCreateWithFlags(&s_rel, cudaStreamNonBlocking);
        cudaEventCreateWithFlags(&e_fork, cudaEventDisableTiming);
        cudaEventCreateWithFlags(&e_rel,  cudaEventDisableTiming);
    }
} s_init;

__device__ __forceinline__ uint32_t smem_u32(const void* p) {
    uint32_t a;
    asm("{ .reg .u64 t; cvta.to.shared.u64 t, %1; cvt.u32.u64 %0, t; }" : "=r"(a) : "l"(p));
    return a;
}

#define CP16(dst, src) \
    asm volatile("cp.async.cg.shared.global [%0], [%1], 16;" :: "r"(dst), "l"(src))
#define CP_COMMIT() asm volatile("cp.async.commit_group;" ::: "memory")
#define CP_WAIT(n)  asm volatile("cp.async.wait_group %0;" :: "n"(n) : "memory")

#define LDSM4(r0, r1, r2, r3, addr) \
    asm volatile("ldmatrix.sync.aligned.m8n8.x4.shared.b16 {%0,%1,%2,%3}, [%4];" \
        : "=r"(r0), "=r"(r1), "=r"(r2), "=r"(r3) : "r"(addr))

__device__ __forceinline__ void mma16816(float* c, const uint32_t* a, const uint32_t* b) {
    asm volatile("mma.sync.aligned.m16n8k16.row.col.f32.bf16.bf16.f32 "
        "{%0,%1,%2,%3}, {%4,%5,%6,%7}, {%8,%9}, {%0,%1,%2,%3};"
        : "+f"(c[0]), "+f"(c[1]), "+f"(c[2]), "+f"(c[3])
        : "r"(a[0]), "r"(a[1]), "r"(a[2]), "r"(a[3]), "r"(b[0]), "r"(b[1]));
}

// BK=64: rows are 64 bf16 = 128B, padded to 144B (rows start at bank r*4 mod 32)
#define TSTRIDE 144
#define ATILEB  (128 * TSTRIDE)            // 18432
#define BTILEB  (64 * TSTRIDE)             // 9216
#define STAGEB  (2 * ATILEB + 2 * BTILEB)  // 55296
#define NSTAGE  3
#define SMEM_GEMM (NSTAGE * STAGEB)        // 165888

#define OFF_AH 0
#define OFF_AL ATILEB
#define OFF_BH (2 * ATILEB)
#define OFF_BL (2 * ATILEB + BTILEB)

enum { EP_SCORE = 0, EP_PART = 1, EP_WEFFT = 2, EP_OUT = 3 };

__device__ __forceinline__ void issue_tileA(uint32_t sdst,
        const __nv_bfloat16* __restrict__ G, int ld, int r0, int k0, int t) {
#pragma unroll
    for (int q = 0; q < 4; q++) {
        const int idx = t + (q << 8);
        const int r = idx >> 3, ch = idx & 7;
        CP16(sdst + r * TSTRIDE + ch * 16,
             G + (size_t)(r0 + r) * ld + k0 + ch * 8);
    }
}
__device__ __forceinline__ void issue_tileB(uint32_t sdst,
        const __nv_bfloat16* __restrict__ G, int ld, int r0, int k0, int t) {
#pragma unroll
    for (int q = 0; q < 2; q++) {
        const int idx = t + (q << 8);
        const int r = idx >> 3, ch = idx & 7;
        CP16(sdst + r * TSTRIDE + ch * 16,
             G + (size_t)(r0 + r) * ld + k0 + ch * 8);
    }
}

__device__ __forceinline__ void store_hilo(__nv_bfloat16* Ch, __nv_bfloat16* Cl,
        int ldc, int row, int col, float v0, float v1) {
    __nv_bfloat16 h0 = __float2bfloat16(v0);
    __nv_bfloat16 h1 = __float2bfloat16(v1);
    __nv_bfloat162 hp; hp.x = h0; hp.y = h1;
    __nv_bfloat162 lp;
    lp.x = __float2bfloat16(v0 - __bfloat162float(h0));
    lp.y = __float2bfloat16(v1 - __bfloat162float(h1));
    *(__nv_bfloat162*)(Ch + (size_t)row * ldc + col) = hp;
    *(__nv_bfloat162*)(Cl + (size_t)row * ldc + col) = lp;
}

template <int EPI>
__global__ __launch_bounds__(256, 1)
void gemm_bf16x3(
    const __nv_bfloat16* __restrict__ Ah, const __nv_bfloat16* __restrict__ Al, int lda,
    const __nv_bfloat16* __restrict__ Bh, const __nv_bfloat16* __restrict__ Bl, int ldb,
    int Kper,
    float* __restrict__ Cf, __nv_bfloat16* __restrict__ Ch, __nv_bfloat16* __restrict__ Cl,
    int ldc,
    const float* __restrict__ aux1, const float* __restrict__ aux2,
    const float* __restrict__ aux3, int auxld, size_t partStride)
{
    extern __shared__ __align__(128) char sm[];
    const uint32_t sbase = smem_u32(sm);
    const int t = threadIdx.x, lane = t & 31, wid = t >> 5;
    const int wm = wid >> 1, wn = wid & 1;
    const int m0 = blockIdx.y * 128, n0 = blockIdx.x * 64;
    const int Koff = blockIdx.z * Kper;
    const int nch = Kper >> 6;

    float acc[2][4][4] = {};
    // fragment double buffer across k-steps
    uint32_t fAh[2][2][4], fAl[2][2][4], fBh[2][4][2], fBl[2][4][2];

#pragma unroll
    for (int c = 0; c < 2; c++) {
        const uint32_t sb = sbase + c * STAGEB;
        issue_tileA(sb + OFF_AH, Ah, lda, m0, Koff + c * 64, t);
        issue_tileA(sb + OFF_AL, Al, lda, m0, Koff + c * 64, t);
        issue_tileB(sb + OFF_BH, Bh, ldb, n0, Koff + c * 64, t);
        issue_tileB(sb + OFF_BL, Bl, ldb, n0, Koff + c * 64, t);
        CP_COMMIT();
    }

    const uint32_t a_off = (uint32_t)((lane & 15) * TSTRIDE + (lane >> 4) * 16)
                         + (uint32_t)(wm * 32 * TSTRIDE);
    const uint32_t b_off = (uint32_t)(((lane & 7) + ((lane >> 4) & 1) * 8) * TSTRIDE
                                      + ((lane >> 3) & 1) * 16)
                         + (uint32_t)(wn * 32 * TSTRIDE);

    for (int c = 0; c < nch; c++) {
        CP_WAIT(1);
        __syncthreads();
        if (c + 2 < nch) {
            const uint32_t sb = sbase + ((c + 2) % NSTAGE) * STAGEB;
            issue_tileA(sb + OFF_AH, Ah, lda, m0, Koff + (c + 2) * 64, t);
            issue_tileA(sb + OFF_AL, Al, lda, m0, Koff + (c + 2) * 64, t);
            issue_tileB(sb + OFF_BH, Bh, ldb, n0, Koff + (c + 2) * 64, t);
            issue_tileB(sb + OFF_BL, Bl, ldb, n0, Koff + (c + 2) * 64, t);
        }
        CP_COMMIT();

        const uint32_t sb = sbase + (c % NSTAGE) * STAGEB;
        const uint32_t sAh = sb + OFF_AH + a_off;
        const uint32_t sAl = sb + OFF_AL + a_off;
        const uint32_t sBh = sb + OFF_BH + b_off;
        const uint32_t sBl = sb + OFF_BL + b_off;

        // load k-step 0 fragments
#pragma unroll
        for (int mi = 0; mi < 2; mi++) {
            const uint32_t ao = mi * 16 * TSTRIDE;
            LDSM4(fAh[0][mi][0], fAh[0][mi][1], fAh[0][mi][2], fAh[0][mi][3], sAh + ao);
            LDSM4(fAl[0][mi][0], fAl[0][mi][1], fAl[0][mi][2], fAl[0][mi][3], sAl + ao);
        }
#pragma unroll
        for (int np = 0; np < 2; np++) {
            const uint32_t bo = np * 16 * TSTRIDE;
            LDSM4(fBh[0][np*2][0], fBh[0][np*2][1], fBh[0][np*2+1][0], fBh[0][np*2+1][1], sBh + bo);
            LDSM4(fBl[0][np*2][0], fBl[0][np*2][1], fBl[0][np*2+1][0], fBl[0][np*2+1][1], sBl + bo);
        }

#pragma unroll
        for (int ks = 0; ks < 4; ks++) {
            const int cur = ks & 1, nxt = cur ^ 1;
            if (ks < 3) {   // prefetch next k-step fragments before MMAs
                const uint32_t ko = (uint32_t)(ks + 1) * 32;
#pragma unroll
                for (int mi = 0; mi < 2; mi++) {
                    const uint32_t ao = mi * 16 * TSTRIDE + ko;
                    LDSM4(fAh[nxt][mi][0], fAh[nxt][mi][1], fAh[nxt][mi][2], fAh[nxt][mi][3], sAh + ao);
                    LDSM4(fAl[nxt][mi][0], fAl[nxt][mi][1], fAl[nxt][mi][2], fAl[nxt][mi][3], sAl + ao);
                }
#pragma unroll
                for (int np = 0; np < 2; np++) {
                    const uint32_t bo = np * 16 * TSTRIDE + ko;
                    LDSM4(fBh[nxt][np*2][0], fBh[nxt][np*2][1], fBh[nxt][np*2+1][0], fBh[nxt][np*2+1][1], sBh + bo);
                    LDSM4(fBl[nxt][np*2][0], fBl[nxt][np*2][1], fBl[nxt][np*2+1][0], fBl[nxt][np*2+1][1], sBl + bo);
                }
            }
#pragma unroll
            for (int mi = 0; mi < 2; mi++)
#pragma unroll
                for (int nj = 0; nj < 4; nj++) {
                    mma16816(acc[mi][nj], fAh[cur][mi], fBh[cur][nj]);
                    mma16816(acc[mi][nj], fAh[cur][mi], fBl[cur][nj]);
                    mma16816(acc[mi][nj], fAl[cur][mi], fBh[cur][nj]);
                }
        }
    }

    __syncthreads();

    const int g = lane >> 2, tq = lane & 3;

    if (EPI == EP_SCORE) {
        float pl[2];
#pragma unroll
        for (int mi = 0; mi < 2; mi++) {
            float p0 = 0.f, p8 = 0.f;
#pragma unroll
            for (int nj = 0; nj < 4; nj++) {
                const int C = n0 + wn * 32 + nj * 8 + tq * 2;
                const int a = C >> 1;
                const float bva = aux1[a], bua = aux2[a], waa = aux3[a];
                {
                    float v = tanhf(acc[mi][nj][0] + bva);
                    float u = acc[mi][nj][1] + bua;
                    u = 1.f / (1.f + __expf(-u));
                    p0 = fmaf(v * u, waa, p0);
                }
                {
                    float v = tanhf(acc[mi][nj][2] + bva);
                    float u = acc[mi][nj][3] + bua;
                    u = 1.f / (1.f + __expf(-u));
                    p8 = fmaf(v * u, waa, p8);
                }
            }
            pl[0] = p0; pl[1] = p8;
#pragma unroll
            for (int o = 1; o <= 2; o <<= 1) {
                pl[0] += __shfl_xor_sync(0xffffffffu, pl[0], o);
                pl[1] += __shfl_xor_sync(0xffffffffu, pl[1], o);
            }
            if (tq == 0) {
                const int cb = blockIdx.x * 2 + wn;
                const int row = m0 + wm * 32 + mi * 16 + g;
                Cf[(size_t)cb * 2048 + row] = pl[0];
                Cf[(size_t)cb * 2048 + row + 8] = pl[1];
            }
        }
        return;
    }

#pragma unroll
    for (int mi = 0; mi < 2; mi++) {
#pragma unroll
        for (int nj = 0; nj < 4; nj++) {
            const int row = m0 + wm * 32 + mi * 16 + g;
            const int col = n0 + wn * 32 + nj * 8 + tq * 2;
            float v00 = acc[mi][nj][0], v01 = acc[mi][nj][1];
            float v10 = acc[mi][nj][2], v11 = acc[mi][nj][3];
            if (EPI == EP_PART) {
                float* dst = Cf + blockIdx.z * partStride;
                *(float2*)(dst + (size_t)row * ldc + col) = make_float2(v00, v01);
                *(float2*)(dst + (size_t)(row + 8) * ldc + col) = make_float2(v10, v11);
            } else if (EPI == EP_OUT) {
                const float b0 = aux1[col], b1 = aux1[col + 1];
                *(float2*)(Cf + (size_t)row * ldc + col) = make_float2(v00 + b0, v01 + b1);
                *(float2*)(Cf + (size_t)(row + 8) * ldc + col) = make_float2(v10 + b0, v11 + b1);
            } else {  // EP_WEFFT
                v00 += aux1[(size_t)row * auxld + col];
                v01 += aux1[(size_t)row * auxld + col + 1];
                v10 += aux1[(size_t)(row + 8) * auxld + col];
                v11 += aux1[(size_t)(row + 8) * auxld + col + 1];
                store_hilo(Ch, Cl, ldc, row, col, v00, v01);
                store_hilo(Ch, Cl, ldc, row + 8, col, v10, v11);
            }
        }
    }
}

// ---------------- helpers ----------------
__device__ __forceinline__ void split4(const float* vv, __nv_bfloat16* dh,
                                       __nv_bfloat16* dl, size_t o) {
#pragma unroll
    for (int x = 0; x < 4; x += 2) {
        __nv_bfloat16 h0 = __float2bfloat16(vv[x]);
        __nv_bfloat16 h1 = __float2bfloat16(vv[x + 1]);
        __nv_bfloat162 hp; hp.x = h0; hp.y = h1;
        __nv_bfloat162 lp;
        lp.x = __float2bfloat16(vv[x] - __bfloat162float(h0));
        lp.y = __float2bfloat16(vv[x + 1] - __bfloat162float(h1));
        *(__nv_bfloat162*)(dh + o + x) = hp;
        *(__nv_bfloat162*)(dl + o + x) = lp;
    }
}

__global__ __launch_bounds__(256) void fuse_cg(
    const float* __restrict__ p, __nv_bfloat16* __restrict__ ch, __nv_bfloat16* __restrict__ cl)
{
    const size_t base = ((size_t)blockIdx.x * 256 + threadIdx.x) * 4;
    float4 s = *(const float4*)(p + base);
#pragma unroll
    for (int z = 1; z < 4; z++) {
        const float4 q = *(const float4*)(p + (size_t)z * 262144 + base);
        s.x += q.x; s.y += q.y; s.z += q.z; s.w += q.w;
    }
    split4((const float*)&s, ch, cl, base);
}

__global__ __launch_bounds__(256) void fuse_m2(
    const float* __restrict__ p, const float* __restrict__ part,
    const float* __restrict__ br,
    __nv_bfloat16* __restrict__ mh, __nv_bfloat16* __restrict__ ml)
{
    const size_t base = ((size_t)blockIdx.x * 256 + threadIdx.x) * 4;
    const int n = (int)(base & 511), m = (int)(base >> 9);
    float4 s = *(const float4*)(p + base);
    const float4 q = *(const float4*)(p + 524288 + base);
    float sv[4] = {s.x + q.x, s.y + q.y, s.z + q.z, s.w + q.w};
    const float bm = br[m];
#pragma unroll
    for (int x = 0; x < 4; x++) {
        float cs = 0.f;
#pragma unroll
        for (int pp = 0; pp < 8; pp++) cs += part[pp * 512 + n + x];
        sv[x] = fmaf(bm, cs, sv[x]);
    }
    split4(sv, mh, ml, base);
}

__global__ __launch_bounds__(256) void convA(
    const float* __restrict__ mention, const float* __restrict__ Wv,
    const float* __restrict__ Wu,
    __nv_bfloat16* __restrict__ mhi, __nv_bfloat16* __restrict__ mlo,
    __nv_bfloat16* __restrict__ wvuh, __nv_bfloat16* __restrict__ wvul)
{
    const int blk = blockIdx.x, t = threadIdx.x;
    if (blk < 2048) {
        const size_t i = (size_t)blk * 1024 + t * 4;
        float4 v = *(const float4*)(mention + i);
        split4((const float*)&v, mhi, mlo, i);
    } else if (blk < 2304) {
        const int r = blk - 2048;
        const size_t si = (size_t)r * 1024 + t * 4;
        float4 v = *(const float4*)(Wv + si);
        split4((const float*)&v, wvuh, wvul, (size_t)(2 * r) * 1024 + t * 4);
    } else {
        const int r = blk - 2304;
        const size_t si = (size_t)r * 1024 + t * 4;
        float4 v = *(const float4*)(Wu + si);
        split4((const float*)&v, wvuh, wvul, (size_t)(2 * r + 1) * 1024 + t * 4);
    }
}

__global__ __launch_bounds__(256) void convB(
    const float* __restrict__ Wr, const float* __restrict__ Wo,
    __nv_bfloat16* __restrict__ wrh, __nv_bfloat16* __restrict__ wrl,
    __nv_bfloat16* __restrict__ wo2h, __nv_bfloat16* __restrict__ wo2l)
{
    const int blk = blockIdx.x, t = threadIdx.x;
    if (blk < 512) {
        const size_t i = (size_t)blk * 1024 + t * 4;
        float4 v = *(const float4*)(Wr + i);
        split4((const float*)&v, wrh, wrl, i);
    } else {
        const size_t li = (size_t)(blk - 512) * 1024 + t * 4;
        const int r = (int)(li >> 9), c = (int)(li & 511);
        float4 v = *(const float4*)(Wo + 1024 + (size_t)r * 1536 + c);
        split4((const float*)&v, wo2h, wo2l, (size_t)r * 512 + c);
    }
}

__global__ __launch_bounds__(256) void convT_hilo(
    const float* __restrict__ RM, __nv_bfloat16* __restrict__ dh, __nv_bfloat16* __restrict__ dl)
{
    __shared__ float tb[32][33];
    const int tx = threadIdx.x, ty = threadIdx.y;
    const int k0 = blockIdx.x * 32, i0 = blockIdx.y * 32;
#pragma unroll
    for (int q = 0; q < 4; q++)
        tb[ty + q * 8][tx] = RM[(size_t)(k0 + ty + q * 8) * 512 + i0 + tx];
    __syncthreads();
#pragma unroll
    for (int q = 0; q < 4; q++) {
        float v = tb[tx][ty + q * 8];
        size_t o = (size_t)(i0 + ty + q * 8) * 1024 + k0 + tx;
        __nv_bfloat16 h = __float2bfloat16(v);
        dh[o] = h;
        dl[o] = __float2bfloat16(v - __bfloat162float(h));
    }
}

__global__ __launch_bounds__(256) void pool2(
    const float* __restrict__ mention, const int* __restrict__ ent,
    const int* __restrict__ msk, const float* __restrict__ g16,
    const float* __restrict__ ba,
    __nv_bfloat16* __restrict__ Eh, __nv_bfloat16* __restrict__ El)
{
    const int be = blockIdx.x, b = be >> 7, tid = threadIdx.x;
    __shared__ float w[16];
    __shared__ int idx[16];
    if (tid < 16) {
        const int id = ent[(size_t)be * 16 + tid];
        idx[tid] = id;
        if (msk[(size_t)be * 16 + tid]) {
            float gs = ba[0];
            const int row = b * 256 + id;
#pragma unroll
            for (int cb = 0; cb < 16; cb++) gs += g16[cb * 2048 + row];
            w[tid] = gs;
        } else {
            w[tid] = -1e25f;
        }
    }
    __syncthreads();
    if (tid == 0) {
        float mx = -INFINITY;
#pragma unroll
        for (int k = 0; k < 16; k++) mx = fmaxf(mx, w[k]);
        float e[16], sum = 0.f;
#pragma unroll
        for (int k = 0; k < 16; k++) { e[k] = expf(w[k] - mx); sum += e[k]; }
        const float inv = 1.f / sum;
#pragma unroll
        for (int k = 0; k < 16; k++) w[k] = e[k] * inv;
    }
    __syncthreads();
    const float* mb = mention + (size_t)b * 256 * 1024;
    const int h0 = tid * 4;
    float4 acc = make_float4(0.f, 0.f, 0.f, 0.f);
#pragma unroll
    for (int k = 0; k < 16; k++) {
        const float4 v = *(const float4*)(mb + (size_t)idx[k] * 1024 + h0);
        const float wk = w[k];
        acc.x = fmaf(wk, v.x, acc.x);
        acc.y = fmaf(wk, v.y, acc.y);
        acc.z = fmaf(wk, v.z, acc.z);
        acc.w = fmaf(wk, v.w, acc.w);
    }
    split4((const float*)&acc, Eh, El, (size_t)be * 1024 + h0);
}

__global__ __launch_bounds__(512) void colsum_part(
    const float* __restrict__ RM, float* __restrict__ part)
{
    const int j = threadIdx.x;
    const int p = blockIdx.x;
    float s = 0.f;
#pragma unroll 4
    for (int r = 0; r < 128; r++) s += RM[(size_t)(p * 128 + r) * 512 + j];
    part[p * 512 + j] = s;
}

// ---------------- launch ----------------
extern "C" void kernel_launch(void* const* d_in, const int* in_sizes, int n_in,
                              void* d_out, int out_size)
{
    const float* mention  = (const float*)d_in[0];
    const int*   entities = (const int*)d_in[1];
    const int*   masks    = (const int*)d_in[2];
    const float* RM       = (const float*)d_in[3];
    const float* Wv       = (const float*)d_in[4];
    const float* bv       = (const float*)d_in[5];
    const float* Wu       = (const float*)d_in[6];
    const float* bu       = (const float*)d_in[7];
    const float* Wa       = (const float*)d_in[8];
    const float* ba       = (const float*)d_in[9];
    const float* Wr       = (const float*)d_in[10];
    const float* br       = (const float*)d_in[11];
    const float* Wo       = (const float*)d_in[12];
    const float* bo       = (const float*)d_in[13];
    float* out = (float*)d_out;

    __nv_bfloat16 *mhi, *mlo, *wvuh, *wvul, *rmth, *rmtl, *wrh, *wrl, *wo2h, *wo2l;
    __nv_bfloat16 *cgh, *cgl, *m2h, *m2l, *wth, *wtl, *eh, *el;
    float *parena, *g16, *part;
    cudaGetSymbolAddress((void**)&mhi, g_mhi);   cudaGetSymbolAddress((void**)&mlo, g_mlo);
    cudaGetSymbolAddress((void**)&wvuh, g_wvuh); cudaGetSymbolAddress((void**)&wvul, g_wvul);
    cudaGetSymbolAddress((void**)&rmth, g_rmth); cudaGetSymbolAddress((void**)&rmtl, g_rmtl);
    cudaGetSymbolAddress((void**)&wrh, g_wrh);   cudaGetSymbolAddress((void**)&wrl, g_wrl);
    cudaGetSymbolAddress((void**)&wo2h, g_wo2h); cudaGetSymbolAddress((void**)&wo2l, g_wo2l);
    cudaGetSymbolAddress((void**)&cgh, g_cgh);   cudaGetSymbolAddress((void**)&cgl, g_cgl);
    cudaGetSymbolAddress((void**)&m2h, g_m2h);   cudaGetSymbolAddress((void**)&m2l, g_m2l);
    cudaGetSymbolAddress((void**)&wth, g_wth);   cudaGetSymbolAddress((void**)&wtl, g_wtl);
    cudaGetSymbolAddress((void**)&eh, g_eh);     cudaGetSymbolAddress((void**)&el, g_el);
    cudaGetSymbolAddress((void**)&parena, g_P);
    cudaGetSymbolAddress((void**)&g16, g_g16);
    cudaGetSymbolAddress((void**)&part, g_part);

    cudaFuncSetAttribute(gemm_bf16x3<EP_SCORE>, cudaFuncAttributeMaxDynamicSharedMemorySize, SMEM_GEMM);
    cudaFuncSetAttribute(gemm_bf16x3<EP_PART>,  cudaFuncAttributeMaxDynamicSharedMemorySize, SMEM_GEMM);
    cudaFuncSetAttribute(gemm_bf16x3<EP_WEFFT>, cudaFuncAttributeMaxDynamicSharedMemorySize, SMEM_GEMM);
    cudaFuncSetAttribute(gemm_bf16x3<EP_OUT>,   cudaFuncAttributeMaxDynamicSharedMemorySize, SMEM_GEMM);

    cudaEventRecord(e_fork, 0);
    cudaStreamWaitEvent(s_rel, e_fork, 0);

    // ---- relation chain (s_rel) ----
    convB<<<1024, 256, 0, s_rel>>>(Wr, Wo, wrh, wrl, wo2h, wo2l);
    convT_hilo<<<dim3(32, 16), dim3(32, 8), 0, s_rel>>>(RM, rmth, rmtl);
    colsum_part<<<8, 512, 0, s_rel>>>(RM, part);
    gemm_bf16x3<EP_PART><<<dim3(8, 4, 4), 256, SMEM_GEMM, s_rel>>>(
        rmth, rmtl, 1024, rmth, rmtl, 1024, 256, parena, nullptr, nullptr, 512,
        nullptr, nullptr, nullptr, 0, (size_t)512 * 512);
    fuse_cg<<<256, 256, 0, s_rel>>>(parena, cgh, cgl);
    gemm_bf16x3<EP_PART><<<dim3(8, 8, 2), 256, SMEM_GEMM, s_rel>>>(
        wrh, wrl, 512, cgh, cgl, 512, 256, parena, nullptr, nullptr, 512,
        nullptr, nullptr, nullptr, 0, (size_t)1024 * 512);
    fuse_m2<<<512, 256, 0, s_rel>>>(parena, part, br, m2h, m2l);
    gemm_bf16x3<EP_WEFFT><<<dim3(16, 8), 256, SMEM_GEMM, s_rel>>>(
        wo2h, wo2l, 512, m2h, m2l, 512, 512, nullptr, wth, wtl, 1024,
        Wo, nullptr, nullptr, 1536, 0);
    cudaEventRecord(e_rel, s_rel);

    // ---- attention chain (legacy stream) ----
    convA<<<2560, 256>>>(mention, Wv, Wu, mhi, mlo, wvuh, wvul);
    gemm_bf16x3<EP_SCORE><<<dim3(8, 16), 256, SMEM_GEMM>>>(
        mhi, mlo, 1024, wvuh, wvul, 1024, 1024, g16, nullptr, nullptr, 0,
        bv, bu, Wa, 0, 0);
    pool2<<<1024, 256>>>(mention, entities, masks, g16, ba, eh, el);

    cudaStreamWaitEvent(0, e_rel, 0);
    gemm_bf16x3<EP_OUT><<<dim3(16, 8), 256, SMEM_GEMM>>>(
        eh, el, 1024, wth, wtl, 1024, 1024, out, nullptr, nullptr, 1024,
        bo, nullptr, nullptr, 0, 0);
}